// round 6
// baseline (speedup 1.0000x reference)
#include <cuda_runtime.h>

// Problem constants
#define BB 1024
#define TT 512
#define DD 128

// Scratch for the hoisted x-side GEMM results (legal: __device__ globals).
// g_xg[m][j] = x_m @ Wg_x + gate_bias   (j in [0,256))
// g_xc[m][j] = x_m @ Wc_x + cand_bias   (j in [0,128))
static __device__ float g_xg[134217728];  // B*T*256  (512 MB)
static __device__ float g_xc[67108864];   // B*T*128  (256 MB)

// Packed dual fp32 FMA (Blackwell f32x2 pipe; 2x FFMA throughput)
__device__ __forceinline__ float2 ffma2(float2 a, float2 b, float2 c) {
    unsigned long long ua = *reinterpret_cast<unsigned long long*>(&a);
    unsigned long long ub = *reinterpret_cast<unsigned long long*>(&b);
    unsigned long long uc = *reinterpret_cast<unsigned long long*>(&c);
    unsigned long long ud;
    asm("fma.rn.f32x2 %0, %1, %2, %3;" : "=l"(ud) : "l"(ua), "l"(ub), "l"(uc));
    return *reinterpret_cast<float2*>(&ud);
}

__device__ __forceinline__ float fsigmoid(float x) {
    return 1.0f / (1.0f + __expf(-x));
}

// ---------------------------------------------------------------------------
// Kernel 1: precompute  [B*T,128] @ [128, 384]  (gate x-half cols 0..255,
// cand x-half cols 256..383), bias fused.  Classic register-blocked SGEMM,
// BM=128 BN=128 BK=16, TM=TN=8, 256 threads, FFMA2 inner loop.
// grid = (M/128, 3)
// ---------------------------------------------------------------------------
__global__ void __launch_bounds__(256) pre_kernel(
    const float* __restrict__ X,
    const float* __restrict__ gk, const float* __restrict__ gb,
    const float* __restrict__ ck, const float* __restrict__ cb)
{
    __shared__ float As[16][132];   // A transposed, padded vs bank conflicts
    __shared__ float Bs[16][128];

    const int nb  = blockIdx.y;             // 0,1: gate col-halves; 2: cand
    const int m0  = blockIdx.x * 128;
    const int tid = threadIdx.x;
    const int tx  = tid & 15, ty = tid >> 4;

    float2 acc[8][4];
    #pragma unroll
    for (int m = 0; m < 8; m++)
        #pragma unroll
        for (int n = 0; n < 4; n++) acc[m][n] = make_float2(0.f, 0.f);

    for (int k0 = 0; k0 < 128; k0 += 16) {
        #pragma unroll
        for (int r = 0; r < 2; r++) {
            int id = tid + r * 256;
            int row = id >> 2, c4 = (id & 3) << 2;
            float4 v = *reinterpret_cast<const float4*>(&X[(size_t)(m0 + row) * 128 + k0 + c4]);
            As[c4 + 0][row] = v.x; As[c4 + 1][row] = v.y;
            As[c4 + 2][row] = v.z; As[c4 + 3][row] = v.w;
        }
        #pragma unroll
        for (int r = 0; r < 2; r++) {
            int id = tid + r * 256;
            int row = id >> 5, col = (id & 31) << 2;
            float4 v;
            if (nb < 2) v = *reinterpret_cast<const float4*>(&gk[(k0 + row) * 256 + nb * 128 + col]);
            else        v = *reinterpret_cast<const float4*>(&ck[(k0 + row) * 128 + col]);
            *reinterpret_cast<float4*>(&Bs[row][col]) = v;
        }
        __syncthreads();
        #pragma unroll
        for (int k = 0; k < 16; k++) {
            float4 a0 = *reinterpret_cast<float4*>(&As[k][ty * 8]);
            float4 a1 = *reinterpret_cast<float4*>(&As[k][ty * 8 + 4]);
            float4 b0 = *reinterpret_cast<float4*>(&Bs[k][tx * 8]);
            float4 b1 = *reinterpret_cast<float4*>(&Bs[k][tx * 8 + 4]);
            float am[8] = {a0.x, a0.y, a0.z, a0.w, a1.x, a1.y, a1.z, a1.w};
            float2 bp[4] = {make_float2(b0.x, b0.y), make_float2(b0.z, b0.w),
                            make_float2(b1.x, b1.y), make_float2(b1.z, b1.w)};
            #pragma unroll
            for (int m = 0; m < 8; m++) {
                float2 av = make_float2(am[m], am[m]);
                #pragma unroll
                for (int n = 0; n < 4; n++) acc[m][n] = ffma2(av, bp[n], acc[m][n]);
            }
        }
        __syncthreads();
    }

    const int tn0 = tx * 8;
    float b8[8];
    #pragma unroll
    for (int n = 0; n < 8; n++)
        b8[n] = (nb < 2) ? gb[nb * 128 + tn0 + n] : cb[tn0 + n];

    #pragma unroll
    for (int m = 0; m < 8; m++) {
        int gm = m0 + ty * 8 + m;
        float4 v0 = make_float4(acc[m][0].x + b8[0], acc[m][0].y + b8[1],
                                acc[m][1].x + b8[2], acc[m][1].y + b8[3]);
        float4 v1 = make_float4(acc[m][2].x + b8[4], acc[m][2].y + b8[5],
                                acc[m][3].x + b8[6], acc[m][3].y + b8[7]);
        if (nb < 2) {
            float* o = &g_xg[(size_t)gm * 256 + nb * 128 + tn0];
            *reinterpret_cast<float4*>(o)     = v0;
            *reinterpret_cast<float4*>(o + 4) = v1;
        } else {
            float* o = &g_xc[(size_t)gm * 128 + tn0];
            *reinterpret_cast<float4*>(o)     = v0;
            *reinterpret_cast<float4*>(o + 4) = v1;
        }
    }
}

// ---------------------------------------------------------------------------
// Kernel 2: recurrent scan. 128 CTAs x 8 batch rows, no inter-CTA deps.
// h-side weights transposed + 16B-XOR-swizzled in smem (conflict-free LDS.128).
// Per step: gates (1 col x 8 rows / thread) -> sigmoid -> r*h -> cand
// (2 threads/col x 4 rows) -> tanh -> attention-gated update + mask + store.
// ---------------------------------------------------------------------------
__global__ void __launch_bounds__(256, 1) rec_kernel(
    const float* __restrict__ att,
    const float* __restrict__ gk,
    const float* __restrict__ ck,
    const int*   __restrict__ seqlen,
    float* __restrict__ out)
{
    extern __shared__ float sm[];
    float* Wg  = sm;             // [256][128] (WgT, swizzled)  128 KB
    float* Wc  = Wg + 32768;     // [128][128] (WcT, swizzled)   64 KB
    float* hS  = Wc + 16384;     // [8][128]
    float* rhS = hS + 1024;      // [8][128]
    float* cS  = rhS + 1024;     // [8][128]
    float* aS  = cS + 1024;      // [8]
    int*   lenS = reinterpret_cast<int*>(aS + 8);  // [8]

    const int tid = threadIdx.x;
    const int b0  = blockIdx.x * 8;

    // Load h-side weights transposed with a 16B-granular XOR swizzle:
    // phys = j*128 + ( ((k>>2) ^ (j&31)) <<2 | (k&3) )  ==  j*128 + (k ^ ((j&31)<<2))
    for (int idx = tid; idx < 32768; idx += 256) {
        int k = idx >> 8, j = idx & 255;
        Wg[j * 128 + ((((k >> 2) ^ (j & 31)) << 2) | (k & 3))] = gk[(128 + k) * 256 + j];
    }
    for (int idx = tid; idx < 16384; idx += 256) {
        int k = idx >> 7, j = idx & 127;
        Wc[j * 128 + ((((k >> 2) ^ (j & 31)) << 2) | (k & 3))] = ck[(128 + k) * 128 + j];
    }
    for (int idx = tid; idx < 1024; idx += 256) hS[idx] = 0.0f;
    if (tid < 8) lenS[tid] = seqlen[b0 + tid];
    __syncthreads();

    int tmax = 0;
    #pragma unroll
    for (int i = 0; i < 8; i++) tmax = max(tmax, lenS[i]);

    const int j    = tid;
    const int jc   = tid & 127;
    const int half = tid >> 7;
    const int i0   = half * 4;
    const int swg  = (j & 31) << 2;
    const int swc  = (jc & 31) << 2;
    const float* wgrow = Wg + j * 128;
    const float* wcrow = Wc + jc * 128;
    float u[8];

    for (int t = 0; t < tmax; t++) {
        if (tid < 8) aS[tid] = att[(b0 + tid) * TT + t];

        // ---- gates: gi[i][j] = Xg[i][j] + sum_k h[i][k]*WgT[j][k] ----
        float xg[8];
        #pragma unroll
        for (int i = 0; i < 8; i++)
            xg[i] = g_xg[(size_t)((b0 + i) * TT + t) * 256 + j];

        float2 acc[8];
        #pragma unroll
        for (int i = 0; i < 8; i++) acc[i] = make_float2(0.f, 0.f);

        #pragma unroll 4
        for (int k = 0; k < 128; k += 4) {
            float4 w = *reinterpret_cast<const float4*>(&wgrow[k ^ swg]);
            float2 w01 = make_float2(w.x, w.y);
            float2 w23 = make_float2(w.z, w.w);
            #pragma unroll
            for (int i = 0; i < 8; i++) {
                float4 hv = *reinterpret_cast<const float4*>(&hS[i * 128 + k]);
                acc[i] = ffma2(make_float2(hv.x, hv.y), w01, acc[i]);
                acc[i] = ffma2(make_float2(hv.z, hv.w), w23, acc[i]);
            }
        }
        #pragma unroll
        for (int i = 0; i < 8; i++) {
            float s = fsigmoid(acc[i].x + acc[i].y + xg[i]);
            if (j < 128) rhS[i * 128 + j] = s * hS[i * 128 + j];  // r * h
            else         u[i] = s;                                // update gate
        }
        __syncthreads();

        // ---- candidate: c[i][jc] = tanh(Xc + sum_k rh[i][k]*WcT[jc][k]) ----
        float xc[4];
        #pragma unroll
        for (int q = 0; q < 4; q++)
            xc[q] = g_xc[(size_t)((b0 + i0 + q) * TT + t) * 128 + jc];
        float2 acc2[4];
        #pragma unroll
        for (int q = 0; q < 4; q++) acc2[q] = make_float2(0.f, 0.f);

        #pragma unroll 4
        for (int k = 0; k < 128; k += 4) {
            float4 w = *reinterpret_cast<const float4*>(&wcrow[k ^ swc]);
            float2 w01 = make_float2(w.x, w.y);
            float2 w23 = make_float2(w.z, w.w);
            #pragma unroll
            for (int q = 0; q < 4; q++) {
                float4 rv = *reinterpret_cast<const float4*>(&rhS[(i0 + q) * 128 + k]);
                acc2[q] = ffma2(make_float2(rv.x, rv.y), w01, acc2[q]);
                acc2[q] = ffma2(make_float2(rv.z, rv.w), w23, acc2[q]);
            }
        }
        #pragma unroll
        for (int q = 0; q < 4; q++)
            cS[(i0 + q) * 128 + jc] = tanhf(acc2[q].x + acc2[q].y + xc[q]);
        __syncthreads();

        // ---- update (threads 128..255 hold u in regs) ----
        if (half) {
            #pragma unroll
            for (int i = 0; i < 8; i++) {
                float a  = aS[i];
                float uu = (1.0f - a) * u[i];           // attention-gated update
                float hv = hS[i * 128 + jc];
                float nh = uu * hv + (1.0f - uu) * cS[i * 128 + jc];
                bool  mk = (t < lenS[i]);
                out[(size_t)((b0 + i) * TT + t) * 128 + jc] = mk ? nh : 0.0f;
                hS[i * 128 + jc] = mk ? nh : hv;
            }
        }
        __syncthreads();
    }

    // dynamic_rnn zeroes outputs past the sequence length; t >= tmax >= len[i]
    for (int t = tmax; t < TT; t++) {
        for (int idx = tid; idx < 1024; idx += 256) {
            int i = idx >> 7, d = idx & 127;
            out[(size_t)((b0 + i) * TT + t) * 128 + d] = 0.0f;
        }
    }
}

// ---------------------------------------------------------------------------
extern "C" void kernel_launch(void* const* d_in, const int* in_sizes, int n_in,
                              void* d_out, int out_size) {
    const float* x   = (const float*)d_in[0];   // rnn_input [B,T,D]
    const float* att = (const float*)d_in[1];   // att_score [B,T,1]
    const float* gk  = (const float*)d_in[2];   // gate_kernel [2D,2D]
    const float* gb  = (const float*)d_in[3];   // gate_bias [2D]
    const float* ck  = (const float*)d_in[4];   // cand_kernel [2D,D]
    const float* cb  = (const float*)d_in[5];   // cand_bias [D]
    const int*   sl  = (const int*)d_in[6];     // sequence_length [B,1]
    float* out = (float*)d_out;                 // [B,T,D]

    const size_t smem = (32768 + 16384 + 3 * 1024 + 8) * sizeof(float) + 8 * sizeof(int);
    cudaFuncSetAttribute(rec_kernel, cudaFuncAttributeMaxDynamicSharedMemorySize, (int)smem);

    pre_kernel<<<dim3((BB * TT) / 128, 3), 256>>>(x, gk, gb, ck, cb);
    rec_kernel<<<BB / 8, 256, smem>>>(att, gk, ck, sl, out);
}

// round 8
// speedup vs baseline: 1.0830x; 1.0830x over previous
#include <cuda_runtime.h>

// Problem constants
#define BB 1024
#define TT 512
#define DD 128

// Scratch for the hoisted x-side GEMM results (legal: __device__ globals).
// g_xg[m][j] = x_m @ Wg_x + gate_bias   (j in [0,256))
// g_xc[m][j] = x_m @ Wc_x + cand_bias   (j in [0,128))
static __device__ float g_xg[134217728];  // B*T*256  (512 MB)
static __device__ float g_xc[67108864];   // B*T*128  (256 MB)

// Packed dual fp32 FMA (Blackwell f32x2 pipe; 2x FFMA throughput)
__device__ __forceinline__ float2 ffma2(float2 a, float2 b, float2 c) {
    unsigned long long ua = *reinterpret_cast<unsigned long long*>(&a);
    unsigned long long ub = *reinterpret_cast<unsigned long long*>(&b);
    unsigned long long uc = *reinterpret_cast<unsigned long long*>(&c);
    unsigned long long ud;
    asm("fma.rn.f32x2 %0, %1, %2, %3;" : "=l"(ud) : "l"(ua), "l"(ub), "l"(uc));
    return *reinterpret_cast<float2*>(&ud);
}

__device__ __forceinline__ float fsigmoid(float x) {
    return 1.0f / (1.0f + __expf(-x));
}

// ---------------------------------------------------------------------------
// Kernel 1: precompute  [B*T,128] @ [128, 384]  (gate x-half cols 0..255,
// cand x-half cols 256..383), bias fused.  Register-blocked SGEMM,
// BM=128 BN=128 BK=16, TM=TN=8, 256 threads, FFMA2 inner loop. (unchanged)
// ---------------------------------------------------------------------------
__global__ void __launch_bounds__(256) pre_kernel(
    const float* __restrict__ X,
    const float* __restrict__ gk, const float* __restrict__ gb,
    const float* __restrict__ ck, const float* __restrict__ cb)
{
    __shared__ float As[16][132];
    __shared__ float Bs[16][128];

    const int nb  = blockIdx.y;             // 0,1: gate col-halves; 2: cand
    const int m0  = blockIdx.x * 128;
    const int tid = threadIdx.x;
    const int tx  = tid & 15, ty = tid >> 4;

    float2 acc[8][4];
    #pragma unroll
    for (int m = 0; m < 8; m++)
        #pragma unroll
        for (int n = 0; n < 4; n++) acc[m][n] = make_float2(0.f, 0.f);

    for (int k0 = 0; k0 < 128; k0 += 16) {
        #pragma unroll
        for (int r = 0; r < 2; r++) {
            int id = tid + r * 256;
            int row = id >> 2, c4 = (id & 3) << 2;
            float4 v = *reinterpret_cast<const float4*>(&X[(size_t)(m0 + row) * 128 + k0 + c4]);
            As[c4 + 0][row] = v.x; As[c4 + 1][row] = v.y;
            As[c4 + 2][row] = v.z; As[c4 + 3][row] = v.w;
        }
        #pragma unroll
        for (int r = 0; r < 2; r++) {
            int id = tid + r * 256;
            int row = id >> 5, col = (id & 31) << 2;
            float4 v;
            if (nb < 2) v = *reinterpret_cast<const float4*>(&gk[(k0 + row) * 256 + nb * 128 + col]);
            else        v = *reinterpret_cast<const float4*>(&ck[(k0 + row) * 128 + col]);
            *reinterpret_cast<float4*>(&Bs[row][col]) = v;
        }
        __syncthreads();
        #pragma unroll
        for (int k = 0; k < 16; k++) {
            float4 a0 = *reinterpret_cast<float4*>(&As[k][ty * 8]);
            float4 a1 = *reinterpret_cast<float4*>(&As[k][ty * 8 + 4]);
            float4 b0 = *reinterpret_cast<float4*>(&Bs[k][tx * 8]);
            float4 b1 = *reinterpret_cast<float4*>(&Bs[k][tx * 8 + 4]);
            float am[8] = {a0.x, a0.y, a0.z, a0.w, a1.x, a1.y, a1.z, a1.w};
            float2 bp[4] = {make_float2(b0.x, b0.y), make_float2(b0.z, b0.w),
                            make_float2(b1.x, b1.y), make_float2(b1.z, b1.w)};
            #pragma unroll
            for (int m = 0; m < 8; m++) {
                float2 av = make_float2(am[m], am[m]);
                #pragma unroll
                for (int n = 0; n < 4; n++) acc[m][n] = ffma2(av, bp[n], acc[m][n]);
            }
        }
        __syncthreads();
    }

    const int tn0 = tx * 8;
    float b8[8];
    #pragma unroll
    for (int n = 0; n < 8; n++)
        b8[n] = (nb < 2) ? gb[nb * 128 + tn0 + n] : cb[tn0 + n];

    #pragma unroll
    for (int m = 0; m < 8; m++) {
        int gm = m0 + ty * 8 + m;
        float4 v0 = make_float4(acc[m][0].x + b8[0], acc[m][0].y + b8[1],
                                acc[m][1].x + b8[2], acc[m][1].y + b8[3]);
        float4 v1 = make_float4(acc[m][2].x + b8[4], acc[m][2].y + b8[5],
                                acc[m][3].x + b8[6], acc[m][3].y + b8[7]);
        if (nb < 2) {
            float* o = &g_xg[(size_t)gm * 256 + nb * 128 + tn0];
            *reinterpret_cast<float4*>(o)     = v0;
            *reinterpret_cast<float4*>(o + 4) = v1;
        } else {
            float* o = &g_xc[(size_t)gm * 128 + tn0];
            *reinterpret_cast<float4*>(o)     = v0;
            *reinterpret_cast<float4*>(o + 4) = v1;
        }
    }
}

// ---------------------------------------------------------------------------
// Kernel 2: recurrent scan, 512 threads (16 warps), K-split + 2-col tiling.
//
// Roles (per step):
//   Phase A (all 512): gate partials. Thread (p, kh, rh) computes, for hidden
//     unit p (gate cols j=p [r] and j=p+128 [u], same swizzle), rows rh*4..+3,
//     k-half kh*64..+63.  W rows conflict-free via XOR swizzle; h loads are
//     warp-uniform broadcasts.  Partials -> stage (stride 20 => STS.128 at
//     the 4-cyc crossbar floor).
//   Phase B: gate gather. Thread g sums its 2 k-half partials (1 LDS.128 each),
//     adds pre-loaded g_xg, sigmoid; writes r*h -> rhS or u -> uS.
//   Phase C: cand partials, same structure on rhS/Wc.
//   Phase D: cand gather fused with update/mask/store (tanh, attention-gated
//     update, STG out, h update).
// g_xg / g_xc / att loads for step t are issued at the top of the step so
// their DRAM latency hides under Phase A.
// ---------------------------------------------------------------------------
__global__ void __launch_bounds__(512, 1) rec_kernel(
    const float* __restrict__ att,
    const float* __restrict__ gk,
    const float* __restrict__ ck,
    const int*   __restrict__ seqlen,
    float* __restrict__ out)
{
    extern __shared__ float sm[];
    float* Wg  = sm;             // [256][128] (WgT, swizzled)  128 KB
    float* Wc  = Wg + 32768;     // [128][128] (WcT, swizzled)   64 KB
    float* stg = Wc + 16384;     // stage: gate 2*128*20=5120; cand 2048 (reuse)
    float* hS  = stg + 5120;     // [8][128]
    float* rhS = hS + 1024;      // [8][128]
    float* uS  = rhS + 1024;     // [8][128]
    float* aS  = uS + 1024;      // [8]
    int*   lenS = reinterpret_cast<int*>(aS + 8);  // [8]

    const int tid = threadIdx.x;
    const int b0  = blockIdx.x * 8;

    // Weights transposed, 16B-granular XOR swizzle: phys = k ^ ((j&31)<<2)
    for (int idx = tid; idx < 32768; idx += 512) {
        int k = idx >> 8, j = idx & 255;
        Wg[j * 128 + (k ^ ((j & 31) << 2))] = gk[(128 + k) * 256 + j];
    }
    for (int idx = tid; idx < 16384; idx += 512) {
        int k = idx >> 7, j = idx & 127;
        Wc[j * 128 + (k ^ ((j & 31) << 2))] = ck[(128 + k) * 128 + j];
    }
    for (int idx = tid; idx < 1024; idx += 512) hS[idx] = 0.0f;
    if (tid < 8) lenS[tid] = seqlen[b0 + tid];
    __syncthreads();

    int tmax = 0;
    #pragma unroll
    for (int i = 0; i < 8; i++) tmax = max(tmax, lenS[i]);

    // ---- compute roles ----
    const int p  = tid & 127;          // hidden unit / cand col
    const int kh = (tid >> 7) & 1;     // k half
    const int rh = tid >> 8;           // row half
    const int sw = (p & 31) << 2;
    const float* w0 = Wg + p * 128;          // r column
    const float* w1 = Wg + (p + 128) * 128;  // u column (same swizzle)
    const float* wc = Wc + p * 128;
    const int kb = kh * 64;
    const int r0 = rh * 4;

    // ---- gate-gather roles: output o = tid*4 .. +3 = (gp, grc, gi0..gi0+3)
    const int gp  = tid >> 2;
    const int grc = (tid >> 1) & 1;
    const int gi0 = (tid & 1) * 4;
    const int gj  = grc * 128 + gp;

    // ---- cand-gather/update roles: outputs (ci, cd), (ci, cd+1)
    const int ci = tid >> 6;
    const int cd = (tid & 63) * 2;

    for (int t = 0; t < tmax; t++) {
        // ---- early global loads for this step (latency hidden by Phase A) ----
        float xr[4];
        {
            size_t base = ((size_t)(b0 + gi0) * TT + t) * 256 + gj;
            #pragma unroll
            for (int q = 0; q < 4; q++) xr[q] = g_xg[base + (size_t)q * (TT * 256)];
        }
        float2 xcv = *reinterpret_cast<const float2*>(
            &g_xc[((size_t)(b0 + ci) * TT + t) * 128 + cd]);
        if (tid < 8) aS[tid] = att[(b0 + tid) * TT + t];

        // ---- Phase A: gate partials ----
        float2 a0[4], a1[4];
        #pragma unroll
        for (int ii = 0; ii < 4; ii++) {
            a0[ii] = make_float2(0.f, 0.f);
            a1[ii] = make_float2(0.f, 0.f);
        }
        #pragma unroll 4
        for (int kt = 0; kt < 64; kt += 4) {
            int k  = kb + kt;
            int ks = k ^ sw;
            float4 wv0 = *reinterpret_cast<const float4*>(&w0[ks]);
            float4 wv1 = *reinterpret_cast<const float4*>(&w1[ks]);
            #pragma unroll
            for (int ii = 0; ii < 4; ii++) {
                float4 hv = *reinterpret_cast<const float4*>(&hS[(r0 + ii) * 128 + k]);
                a0[ii] = ffma2(make_float2(hv.x, hv.y), make_float2(wv0.x, wv0.y), a0[ii]);
                a0[ii] = ffma2(make_float2(hv.z, hv.w), make_float2(wv0.z, wv0.w), a0[ii]);
                a1[ii] = ffma2(make_float2(hv.x, hv.y), make_float2(wv1.x, wv1.y), a1[ii]);
                a1[ii] = ffma2(make_float2(hv.z, hv.w), make_float2(wv1.z, wv1.w), a1[ii]);
            }
        }
        {
            float* st = stg + kh * 2560 + p * 20 + r0;
            float4 s0 = make_float4(a0[0].x + a0[0].y, a0[1].x + a0[1].y,
                                    a0[2].x + a0[2].y, a0[3].x + a0[3].y);
            float4 s1 = make_float4(a1[0].x + a1[0].y, a1[1].x + a1[1].y,
                                    a1[2].x + a1[2].y, a1[3].x + a1[3].y);
            *reinterpret_cast<float4*>(st)     = s0;  // r partials
            *reinterpret_cast<float4*>(st + 8) = s1;  // u partials
        }
        __syncthreads();

        // ---- Phase B: gate gather -> sigmoid -> rhS / uS ----
        {
            const float* st = stg + gp * 20 + grc * 8 + gi0;
            float4 va = *reinterpret_cast<const float4*>(st);
            float4 vb = *reinterpret_cast<const float4*>(st + 2560);
            float s0 = fsigmoid(va.x + vb.x + xr[0]);
            float s1 = fsigmoid(va.y + vb.y + xr[1]);
            float s2 = fsigmoid(va.z + vb.z + xr[2]);
            float s3 = fsigmoid(va.w + vb.w + xr[3]);
            if (grc == 0) {
                rhS[(gi0 + 0) * 128 + gp] = s0 * hS[(gi0 + 0) * 128 + gp];
                rhS[(gi0 + 1) * 128 + gp] = s1 * hS[(gi0 + 1) * 128 + gp];
                rhS[(gi0 + 2) * 128 + gp] = s2 * hS[(gi0 + 2) * 128 + gp];
                rhS[(gi0 + 3) * 128 + gp] = s3 * hS[(gi0 + 3) * 128 + gp];
            } else {
                uS[(gi0 + 0) * 128 + gp] = s0;
                uS[(gi0 + 1) * 128 + gp] = s1;
                uS[(gi0 + 2) * 128 + gp] = s2;
                uS[(gi0 + 3) * 128 + gp] = s3;
            }
        }
        __syncthreads();

        // ---- Phase C: cand partials ----
        float2 c2[4];
        #pragma unroll
        for (int ii = 0; ii < 4; ii++) c2[ii] = make_float2(0.f, 0.f);
        #pragma unroll 4
        for (int kt = 0; kt < 64; kt += 4) {
            int k  = kb + kt;
            int ks = k ^ sw;
            float4 wv = *reinterpret_cast<const float4*>(&wc[ks]);
            #pragma unroll
            for (int ii = 0; ii < 4; ii++) {
                float4 rv = *reinterpret_cast<const float4*>(&rhS[(r0 + ii) * 128 + k]);
                c2[ii] = ffma2(make_float2(rv.x, rv.y), make_float2(wv.x, wv.y), c2[ii]);
                c2[ii] = ffma2(make_float2(rv.z, rv.w), make_float2(wv.z, wv.w), c2[ii]);
            }
        }
        #pragma unroll
        for (int ii = 0; ii < 4; ii++)
            stg[kh * 1024 + (r0 + ii) * 128 + p] = c2[ii].x + c2[ii].y;
        __syncthreads();

        // ---- Phase D: cand gather + tanh + attention-gated update + store ----
        {
            float2 q0 = *reinterpret_cast<const float2*>(&stg[ci * 128 + cd]);
            float2 q1 = *reinterpret_cast<const float2*>(&stg[1024 + ci * 128 + cd]);
            float c0 = tanhf(q0.x + q1.x + xcv.x);
            float c1 = tanhf(q0.y + q1.y + xcv.y);
            float a  = aS[ci];
            bool  mk = (t < lenS[ci]);
            float u0 = (1.0f - a) * uS[ci * 128 + cd];
            float u1 = (1.0f - a) * uS[ci * 128 + cd + 1];
            float h0 = hS[ci * 128 + cd];
            float h1 = hS[ci * 128 + cd + 1];
            float n0 = u0 * h0 + (1.0f - u0) * c0;
            float n1 = u1 * h1 + (1.0f - u1) * c1;
            float2 ov = make_float2(mk ? n0 : 0.0f, mk ? n1 : 0.0f);
            *reinterpret_cast<float2*>(&out[((size_t)(b0 + ci) * TT + t) * 128 + cd]) = ov;
            hS[ci * 128 + cd]     = mk ? n0 : h0;
            hS[ci * 128 + cd + 1] = mk ? n1 : h1;
        }
        __syncthreads();
    }

    // dynamic_rnn zeroes outputs past the sequence length; t >= tmax >= len[i]
    for (int t = tmax; t < TT; t++) {
        for (int idx = tid; idx < 1024; idx += 512) {
            int i = idx >> 7, d = idx & 127;
            out[((size_t)(b0 + i) * TT + t) * 128 + d] = 0.0f;
        }
    }
}

// ---------------------------------------------------------------------------
extern "C" void kernel_launch(void* const* d_in, const int* in_sizes, int n_in,
                              void* d_out, int out_size) {
    const float* x   = (const float*)d_in[0];   // rnn_input [B,T,D]
    const float* att = (const float*)d_in[1];   // att_score [B,T,1]
    const float* gk  = (const float*)d_in[2];   // gate_kernel [2D,2D]
    const float* gb  = (const float*)d_in[3];   // gate_bias [2D]
    const float* ck  = (const float*)d_in[4];   // cand_kernel [2D,D]
    const float* cb  = (const float*)d_in[5];   // cand_bias [D]
    const int*   sl  = (const int*)d_in[6];     // sequence_length [B,1]
    float* out = (float*)d_out;                 // [B,T,D]

    // smem floats: Wg 32768 + Wc 16384 + stage 5120 + h/rh/u 3072 + a/len 16
    const size_t smem = (32768 + 16384 + 5120 + 3 * 1024 + 8) * sizeof(float) + 8 * sizeof(int);
    cudaFuncSetAttribute(rec_kernel, cudaFuncAttributeMaxDynamicSharedMemorySize, (int)smem);

    pre_kernel<<<dim3((BB * TT) / 128, 3), 256>>>(x, gk, gb, ck, cb);
    rec_kernel<<<BB / 8, 512, smem>>>(att, gk, ck, sl, out);
}

// round 9
// speedup vs baseline: 1.1364x; 1.0492x over previous
#include <cuda_runtime.h>

// Problem constants
#define BB 1024
#define TT 512
#define DD 128

// Scratch for the hoisted x-side GEMM results (legal: __device__ globals).
static __device__ float g_xg[134217728];  // B*T*256  (512 MB)
static __device__ float g_xc[67108864];   // B*T*128  (256 MB)

// Packed dual fp32 FMA (Blackwell f32x2 pipe; 2x FFMA throughput)
__device__ __forceinline__ float2 ffma2(float2 a, float2 b, float2 c) {
    unsigned long long ua = *reinterpret_cast<unsigned long long*>(&a);
    unsigned long long ub = *reinterpret_cast<unsigned long long*>(&b);
    unsigned long long uc = *reinterpret_cast<unsigned long long*>(&c);
    unsigned long long ud;
    asm("fma.rn.f32x2 %0, %1, %2, %3;" : "=l"(ud) : "l"(ua), "l"(ub), "l"(uc));
    return *reinterpret_cast<float2*>(&ud);
}

__device__ __forceinline__ float fsigmoid(float x) {
    return 1.0f / (1.0f + __expf(-x));
}

__device__ __forceinline__ float2 shfl_red2(float2 v) {
    v.x += __shfl_xor_sync(0xffffffffu, v.x, 1);
    v.y += __shfl_xor_sync(0xffffffffu, v.y, 1);
    return v;
}

// ---------------------------------------------------------------------------
// Kernel 1: precompute  [B*T,128] @ [128, 384], bias fused. (unchanged)
// ---------------------------------------------------------------------------
__global__ void __launch_bounds__(256) pre_kernel(
    const float* __restrict__ X,
    const float* __restrict__ gk, const float* __restrict__ gb,
    const float* __restrict__ ck, const float* __restrict__ cb)
{
    __shared__ float As[16][132];
    __shared__ float Bs[16][128];

    const int nb  = blockIdx.y;             // 0,1: gate col-halves; 2: cand
    const int m0  = blockIdx.x * 128;
    const int tid = threadIdx.x;
    const int tx  = tid & 15, ty = tid >> 4;

    float2 acc[8][4];
    #pragma unroll
    for (int m = 0; m < 8; m++)
        #pragma unroll
        for (int n = 0; n < 4; n++) acc[m][n] = make_float2(0.f, 0.f);

    for (int k0 = 0; k0 < 128; k0 += 16) {
        #pragma unroll
        for (int r = 0; r < 2; r++) {
            int id = tid + r * 256;
            int row = id >> 2, c4 = (id & 3) << 2;
            float4 v = *reinterpret_cast<const float4*>(&X[(size_t)(m0 + row) * 128 + k0 + c4]);
            As[c4 + 0][row] = v.x; As[c4 + 1][row] = v.y;
            As[c4 + 2][row] = v.z; As[c4 + 3][row] = v.w;
        }
        #pragma unroll
        for (int r = 0; r < 2; r++) {
            int id = tid + r * 256;
            int row = id >> 5, col = (id & 31) << 2;
            float4 v;
            if (nb < 2) v = *reinterpret_cast<const float4*>(&gk[(k0 + row) * 256 + nb * 128 + col]);
            else        v = *reinterpret_cast<const float4*>(&ck[(k0 + row) * 128 + col]);
            *reinterpret_cast<float4*>(&Bs[row][col]) = v;
        }
        __syncthreads();
        #pragma unroll
        for (int k = 0; k < 16; k++) {
            float4 a0 = *reinterpret_cast<float4*>(&As[k][ty * 8]);
            float4 a1 = *reinterpret_cast<float4*>(&As[k][ty * 8 + 4]);
            float4 b0 = *reinterpret_cast<float4*>(&Bs[k][tx * 8]);
            float4 b1 = *reinterpret_cast<float4*>(&Bs[k][tx * 8 + 4]);
            float am[8] = {a0.x, a0.y, a0.z, a0.w, a1.x, a1.y, a1.z, a1.w};
            float2 bp[4] = {make_float2(b0.x, b0.y), make_float2(b0.z, b0.w),
                            make_float2(b1.x, b1.y), make_float2(b1.z, b1.w)};
            #pragma unroll
            for (int m = 0; m < 8; m++) {
                float2 av = make_float2(am[m], am[m]);
                #pragma unroll
                for (int n = 0; n < 4; n++) acc[m][n] = ffma2(av, bp[n], acc[m][n]);
            }
        }
        __syncthreads();
    }

    const int tn0 = tx * 8;
    float b8[8];
    #pragma unroll
    for (int n = 0; n < 8; n++)
        b8[n] = (nb < 2) ? gb[nb * 128 + tn0 + n] : cb[tn0 + n];

    #pragma unroll
    for (int m = 0; m < 8; m++) {
        int gm = m0 + ty * 8 + m;
        float4 v0 = make_float4(acc[m][0].x + b8[0], acc[m][0].y + b8[1],
                                acc[m][1].x + b8[2], acc[m][1].y + b8[3]);
        float4 v1 = make_float4(acc[m][2].x + b8[4], acc[m][2].y + b8[5],
                                acc[m][3].x + b8[6], acc[m][3].y + b8[7]);
        if (nb < 2) {
            float* o = &g_xg[(size_t)gm * 256 + nb * 128 + tn0];
            *reinterpret_cast<float4*>(o)     = v0;
            *reinterpret_cast<float4*>(o + 4) = v1;
        } else {
            float* o = &g_xc[(size_t)gm * 128 + tn0];
            *reinterpret_cast<float4*>(o)     = v0;
            *reinterpret_cast<float4*>(o + 4) = v1;
        }
    }
}

// ---------------------------------------------------------------------------
// Kernel 2: recurrent scan, 512 threads, minimal-W-traffic layout.
//
// Partial phases: thread (p, klo, khi) = col p, k-quarter khi*64+klo*32,
//   all 8 rows. W read ONCE per step; h/rh read as 2-address broadcast
//   LDS.128s from interleaved hT[k*8 + (k>>5)*4 + row].
// Reduction: klo via shfl.bfly(1); khi via smem stage (stride 20).
// Gather/update roles: thread (pg=tid>>2, q=tid&3) -> row pair (2q,2q+1).
// ---------------------------------------------------------------------------
__global__ void __launch_bounds__(512, 1) rec_kernel(
    const float* __restrict__ att,
    const float* __restrict__ gk,
    const float* __restrict__ ck,
    const int*   __restrict__ seqlen,
    float* __restrict__ out)
{
    extern __shared__ float sm[];
    float* Wg    = sm;                 // [256][128] swizzled, 128 KB
    float* Wc    = Wg + 32768;         // [128][128] swizzled,  64 KB
    float* stage = Wc + 16384;         // 2 x 128 x 20 = 5120 (20 KB)
    float* hT    = stage + 5120;       // interleaved, 1040
    float* rhT   = hT + 1040;          // 1040
    float* uT    = rhT + 1040;         // 1040
    float* aS    = uT + 1040;          // 8
    int*   lenS  = reinterpret_cast<int*>(aS + 8);   // 8

    const int tid = threadIdx.x;
    const int b0  = blockIdx.x * 8;

    // Weights transposed with double-XOR swizzle:
    // phys(k,j) = k ^ ((j&31)<<2) ^ (((k>>5)&1)<<4)
    for (int idx = tid; idx < 32768; idx += 512) {
        int k = idx >> 8, j = idx & 255;
        int ph = k ^ ((j & 31) << 2) ^ (((k >> 5) & 1) << 4);
        Wg[j * 128 + ph] = gk[(128 + k) * 256 + j];
    }
    for (int idx = tid; idx < 16384; idx += 512) {
        int k = idx >> 7, j = idx & 127;
        int ph = k ^ ((j & 31) << 2) ^ (((k >> 5) & 1) << 4);
        Wc[j * 128 + ph] = ck[(128 + k) * 128 + j];
    }
    for (int idx = tid; idx < 1040; idx += 512) hT[idx] = 0.0f;
    if (tid < 8) lenS[tid] = seqlen[b0 + tid];
    __syncthreads();

    int tmax = 0;
    #pragma unroll
    for (int i = 0; i < 8; i++) tmax = max(tmax, lenS[i]);

    // ---- partial-phase roles ----
    const int klo = tid & 1;
    const int p   = (tid >> 1) & 127;
    const int khi = tid >> 8;
    const int kbase = khi * 64 + klo * 32;
    const int kx  = kbase ^ (((p & 31) << 2) ^ (klo << 4));  // ks = kt ^ kx
    const float* w0 = Wg + p * 128;            // r column
    const float* w1 = w0 + 16384;              // u column (same swizzle)
    const float* wc = Wc + p * 128;
    const int hoff = kbase * 8 + (2 * khi + klo) * 4;        // hT slice base
    float* stp = stage + khi * 2560 + p * 20;

    // ---- gather/update roles ----
    const int pg = tid >> 2;         // col (gate unit / cand dim)
    const int q  = tid & 3;          // row pair (2q, 2q+1)
    const int hp2 = pg * 8 + (pg >> 5) * 4 + 2 * q;          // hT f2 index
    const float* stg_r = stage + pg * 20 + 2 * q;

    for (int t = 0; t < tmax; t++) {
        // ---- early global loads (latency hidden under phase A) ----
        size_t mrow = ((size_t)(b0 + 2 * q) * TT + t);
        float xgr0 = g_xg[mrow * 256 + pg];
        float xgr1 = g_xg[(mrow + TT) * 256 + pg];
        float xgu0 = g_xg[mrow * 256 + pg + 128];
        float xgu1 = g_xg[(mrow + TT) * 256 + pg + 128];
        float xc0  = g_xc[mrow * 128 + pg];
        float xc1  = g_xc[(mrow + TT) * 128 + pg];
        if (tid < 8) aS[tid] = att[(b0 + tid) * TT + t];

        // ---- Phase A: gate partials (cols p, p+128; 8 rows; 32 k) ----
        float2 ar[4], au[4];
        #pragma unroll
        for (int m = 0; m < 4; m++) { ar[m] = make_float2(0.f, 0.f); au[m] = make_float2(0.f, 0.f); }
        {
            const float* hb = hT + hoff;
            #pragma unroll
            for (int kt = 0; kt < 32; kt += 4) {
                int ks = kt ^ kx;
                float4 wr = *reinterpret_cast<const float4*>(w0 + ks);
                float4 wu = *reinterpret_cast<const float4*>(w1 + ks);
                const float wra[4] = {wr.x, wr.y, wr.z, wr.w};
                const float wua[4] = {wu.x, wu.y, wu.z, wu.w};
                #pragma unroll
                for (int jj = 0; jj < 4; jj++) {
                    float4 h03 = *reinterpret_cast<const float4*>(hb + (kt + jj) * 8);
                    float4 h47 = *reinterpret_cast<const float4*>(hb + (kt + jj) * 8 + 4);
                    float2 wr2 = make_float2(wra[jj], wra[jj]);
                    float2 wu2 = make_float2(wua[jj], wua[jj]);
                    ar[0] = ffma2(make_float2(h03.x, h03.y), wr2, ar[0]);
                    ar[1] = ffma2(make_float2(h03.z, h03.w), wr2, ar[1]);
                    ar[2] = ffma2(make_float2(h47.x, h47.y), wr2, ar[2]);
                    ar[3] = ffma2(make_float2(h47.z, h47.w), wr2, ar[3]);
                    au[0] = ffma2(make_float2(h03.x, h03.y), wu2, au[0]);
                    au[1] = ffma2(make_float2(h03.z, h03.w), wu2, au[1]);
                    au[2] = ffma2(make_float2(h47.x, h47.y), wu2, au[2]);
                    au[3] = ffma2(make_float2(h47.z, h47.w), wu2, au[3]);
                }
            }
        }
        #pragma unroll
        for (int m = 0; m < 4; m++) { ar[m] = shfl_red2(ar[m]); au[m] = shfl_red2(au[m]); }
        if (klo == 0) {
            *reinterpret_cast<float4*>(stp)      = make_float4(ar[0].x, ar[0].y, ar[1].x, ar[1].y);
            *reinterpret_cast<float4*>(stp + 4)  = make_float4(ar[2].x, ar[2].y, ar[3].x, ar[3].y);
            *reinterpret_cast<float4*>(stp + 8)  = make_float4(au[0].x, au[0].y, au[1].x, au[1].y);
            *reinterpret_cast<float4*>(stp + 12) = make_float4(au[2].x, au[2].y, au[3].x, au[3].y);
        }
        __syncthreads();

        // ---- Phase B: gate gather -> sigmoid -> rhT / uT ----
        {
            float2 va = *reinterpret_cast<const float2*>(stg_r);
            float2 vb = *reinterpret_cast<const float2*>(stg_r + 2560);
            float2 wa = *reinterpret_cast<const float2*>(stg_r + 8);
            float2 wb = *reinterpret_cast<const float2*>(stg_r + 2568);
            float r0 = fsigmoid(va.x + vb.x + xgr0);
            float r1 = fsigmoid(va.y + vb.y + xgr1);
            float u0 = fsigmoid(wa.x + wb.x + xgu0);
            float u1 = fsigmoid(wa.y + wb.y + xgu1);
            float2 h2 = *reinterpret_cast<const float2*>(hT + hp2);
            *reinterpret_cast<float2*>(rhT + hp2) = make_float2(r0 * h2.x, r1 * h2.y);
            *reinterpret_cast<float2*>(uT + hp2)  = make_float2(u0, u1);
        }
        __syncthreads();

        // ---- Phase C: cand partials (col p; 8 rows; 32 k) ----
        float2 ac[4];
        #pragma unroll
        for (int m = 0; m < 4; m++) ac[m] = make_float2(0.f, 0.f);
        {
            const float* rb = rhT + hoff;
            #pragma unroll
            for (int kt = 0; kt < 32; kt += 4) {
                int ks = kt ^ kx;
                float4 wv = *reinterpret_cast<const float4*>(wc + ks);
                const float wca[4] = {wv.x, wv.y, wv.z, wv.w};
                #pragma unroll
                for (int jj = 0; jj < 4; jj++) {
                    float4 r03 = *reinterpret_cast<const float4*>(rb + (kt + jj) * 8);
                    float4 r47 = *reinterpret_cast<const float4*>(rb + (kt + jj) * 8 + 4);
                    float2 w2 = make_float2(wca[jj], wca[jj]);
                    ac[0] = ffma2(make_float2(r03.x, r03.y), w2, ac[0]);
                    ac[1] = ffma2(make_float2(r03.z, r03.w), w2, ac[1]);
                    ac[2] = ffma2(make_float2(r47.x, r47.y), w2, ac[2]);
                    ac[3] = ffma2(make_float2(r47.z, r47.w), w2, ac[3]);
                }
            }
        }
        #pragma unroll
        for (int m = 0; m < 4; m++) ac[m] = shfl_red2(ac[m]);
        if (klo == 0) {
            *reinterpret_cast<float4*>(stp)     = make_float4(ac[0].x, ac[0].y, ac[1].x, ac[1].y);
            *reinterpret_cast<float4*>(stp + 4) = make_float4(ac[2].x, ac[2].y, ac[3].x, ac[3].y);
        }
        __syncthreads();

        // ---- Phase D: cand gather + tanh + attention-gated update + store ----
        {
            float2 ca = *reinterpret_cast<const float2*>(stg_r);
            float2 cb2 = *reinterpret_cast<const float2*>(stg_r + 2560);
            float c0 = tanhf(ca.x + cb2.x + xc0);
            float c1 = tanhf(ca.y + cb2.y + xc1);
            float a0 = aS[2 * q], a1 = aS[2 * q + 1];
            int   l0 = lenS[2 * q], l1 = lenS[2 * q + 1];
            float2 u2 = *reinterpret_cast<const float2*>(uT + hp2);
            float2 h2 = *reinterpret_cast<const float2*>(hT + hp2);
            float uu0 = (1.0f - a0) * u2.x;
            float uu1 = (1.0f - a1) * u2.y;
            float n0 = uu0 * h2.x + (1.0f - uu0) * c0;
            float n1 = uu1 * h2.y + (1.0f - uu1) * c1;
            bool m0 = (t < l0), m1 = (t < l1);
            out[mrow * 128 + pg]        = m0 ? n0 : 0.0f;
            out[(mrow + TT) * 128 + pg] = m1 ? n1 : 0.0f;
            hT[hp2]     = m0 ? n0 : h2.x;
            hT[hp2 + 1] = m1 ? n1 : h2.y;
        }
        __syncthreads();
    }

    // dynamic_rnn zeroes outputs past the sequence length; t >= tmax >= len[i]
    for (int t = tmax; t < TT; t++) {
        for (int idx = tid; idx < 1024; idx += 512) {
            int i = idx >> 7, d = idx & 127;
            out[((size_t)(b0 + i) * TT + t) * 128 + d] = 0.0f;
        }
    }
}

// ---------------------------------------------------------------------------
extern "C" void kernel_launch(void* const* d_in, const int* in_sizes, int n_in,
                              void* d_out, int out_size) {
    const float* x   = (const float*)d_in[0];   // rnn_input [B,T,D]
    const float* att = (const float*)d_in[1];   // att_score [B,T,1]
    const float* gk  = (const float*)d_in[2];   // gate_kernel [2D,2D]
    const float* gb  = (const float*)d_in[3];   // gate_bias [2D]
    const float* ck  = (const float*)d_in[4];   // cand_kernel [2D,D]
    const float* cb  = (const float*)d_in[5];   // cand_bias [D]
    const int*   sl  = (const int*)d_in[6];     // sequence_length [B,1]
    float* out = (float*)d_out;                 // [B,T,D]

    // smem floats: Wg 32768 + Wc 16384 + stage 5120 + hT/rhT/uT 3120 + a/len 16
    const size_t smem = (32768 + 16384 + 5120 + 3 * 1040 + 8) * sizeof(float) + 8 * sizeof(int);
    cudaFuncSetAttribute(rec_kernel, cudaFuncAttributeMaxDynamicSharedMemorySize, (int)smem);

    pre_kernel<<<dim3((BB * TT) / 128, 3), 256>>>(x, gk, gb, ck, cb);
    rec_kernel<<<BB / 8, 512, smem>>>(att, gk, ck, sl, out);
}

// round 12
// speedup vs baseline: 1.2623x; 1.1108x over previous
#include <cuda_runtime.h>
#include <cuda_bf16.h>
#include <cstdint>

// Problem constants
#define BB 1024
#define TT 512
#define DD 128

// Scratch (legal: __device__ globals).
static __device__ float g_xg[134217728];  // B*T*256 : x@Wg_x + gate_bias
static __device__ float g_xc[67108864];   // B*T*128 : x@Wc_x + cand_bias
// W transposed to [384][128] K-major, split into bf16 hi/lo
static __device__ __nv_bfloat16 g_wthi[49152];
static __device__ __nv_bfloat16 g_wtlo[49152];

// ---------------- helpers ----------------
__device__ __forceinline__ uint32_t smem_u32(const void* p) {
    uint32_t a;
    asm("{ .reg .u64 t; cvta.to.shared.u64 t, %1; cvt.u32.u64 %0, t; }" : "=r"(a) : "l"(p));
    return a;
}
__device__ __forceinline__ void ldsm4(uint32_t* r, uint32_t addr) {
    asm volatile("ldmatrix.sync.aligned.m8n8.x4.shared.b16 {%0,%1,%2,%3}, [%4];"
                 : "=r"(r[0]), "=r"(r[1]), "=r"(r[2]), "=r"(r[3]) : "r"(addr));
}
__device__ __forceinline__ void mma_bf16(float* d, const uint32_t* a, const uint32_t* b) {
    asm volatile(
        "mma.sync.aligned.m16n8k16.row.col.f32.bf16.bf16.f32 "
        "{%0,%1,%2,%3}, {%4,%5,%6,%7}, {%8,%9}, {%0,%1,%2,%3};"
        : "+f"(d[0]), "+f"(d[1]), "+f"(d[2]), "+f"(d[3])
        : "r"(a[0]), "r"(a[1]), "r"(a[2]), "r"(a[3]), "r"(b[0]), "r"(b[1]));
}

// Packed dual fp32 FMA
__device__ __forceinline__ float2 ffma2(float2 a, float2 b, float2 c) {
    unsigned long long ua = *reinterpret_cast<unsigned long long*>(&a);
    unsigned long long ub = *reinterpret_cast<unsigned long long*>(&b);
    unsigned long long uc = *reinterpret_cast<unsigned long long*>(&c);
    unsigned long long ud;
    asm("fma.rn.f32x2 %0, %1, %2, %3;" : "=l"(ud) : "l"(ua), "l"(ub), "l"(uc));
    return *reinterpret_cast<float2*>(&ud);
}
__device__ __forceinline__ float fsigmoid(float x) { return 1.0f / (1.0f + __expf(-x)); }
__device__ __forceinline__ float2 shfl_red2(float2 v) {
    v.x += __shfl_xor_sync(0xffffffffu, v.x, 1);
    v.y += __shfl_xor_sync(0xffffffffu, v.y, 1);
    return v;
}

// ---------------------------------------------------------------------------
// Prep: transpose W to [384][128] K-major and split bf16 hi/lo.
// n<256: gate col n (Wg_x);  n>=256: cand col n-256 (Wc_x).
// ---------------------------------------------------------------------------
__global__ void prep_w(const float* __restrict__ gk, const float* __restrict__ ck) {
    int n = blockIdx.x, k = threadIdx.x;
    float v = (n < 256) ? gk[k * 256 + n] : ck[k * 128 + (n - 256)];
    __nv_bfloat16 h = __float2bfloat16(v);
    g_wthi[n * 128 + k] = h;
    g_wtlo[n * 128 + k] = __float2bfloat16(v - __bfloat162float(h));
}

// ---------------------------------------------------------------------------
// Kernel 1: hoisted x-GEMM on HMMA (mma.sync m16n8k16 bf16, fp32 accum),
// bf16x3 split: Ahi*Bhi + Ahi*Blo + Alo*Bhi.
// Per CTA: M=128 tile of B*T, K=128 resident, 3 N-tiles of 128.
// Warp tile 32x64 (8 warps = 4M x 2N). Smem rows padded to 272B so every
// ldmatrix's 8 row-addresses hit distinct 16B slices (272 mod 128 = 16).
// smem: bias[384f] | Ahi 128x272 | Alo | Bhi 128x272 | Blo
// ---------------------------------------------------------------------------
#define A_HI_OFF 1536
#define A_LO_OFF (A_HI_OFF + 34816)
#define B_HI_OFF (A_LO_OFF + 34816)
#define B_LO_OFF (B_HI_OFF + 34816)
#define PRE_SMEM (B_LO_OFF + 34816)

__global__ void __launch_bounds__(256) pre_mma(
    const float* __restrict__ X,
    const float* __restrict__ gb, const float* __restrict__ cb)
{
    extern __shared__ char smc[];
    const uint32_t sb = smem_u32(smc);
    float* biasS = reinterpret_cast<float*>(smc);
    const int tid  = threadIdx.x;
    const int lane = tid & 31;
    const int wid  = tid >> 5;
    const int wm   = wid & 3;        // M group: rows wm*32..+31
    const int wn   = wid >> 2;       // N group: cols wn*64..+63
    const int m0   = blockIdx.x * 128;

    if (tid < 256) biasS[tid] = gb[tid];
    if (tid < 128) biasS[256 + tid] = cb[tid];

    // ---- A tile: fp32 -> bf16 hi/lo, padded rows (272B) ----
    {
        const int row  = tid >> 1;
        const int half = tid & 1;
        const float* xr = &X[(size_t)(m0 + row) * 128 + half * 64];
        char* Ahi = smc + A_HI_OFF + row * 272 + half * 128;
        char* Alo = smc + A_LO_OFF + row * 272 + half * 128;
        #pragma unroll
        for (int j = 0; j < 16; j++) {
            float4 v = *reinterpret_cast<const float4*>(&xr[j * 4]);
            __nv_bfloat162 h01 = __floats2bfloat162_rn(v.x, v.y);
            __nv_bfloat162 h23 = __floats2bfloat162_rn(v.z, v.w);
            __nv_bfloat162 l01 = __floats2bfloat162_rn(v.x - __bfloat162float(h01.x),
                                                       v.y - __bfloat162float(h01.y));
            __nv_bfloat162 l23 = __floats2bfloat162_rn(v.z - __bfloat162float(h23.x),
                                                       v.w - __bfloat162float(h23.y));
            *reinterpret_cast<uint2*>(Ahi + j * 8) =
                make_uint2(*reinterpret_cast<uint32_t*>(&h01), *reinterpret_cast<uint32_t*>(&h23));
            *reinterpret_cast<uint2*>(Alo + j * 8) =
                make_uint2(*reinterpret_cast<uint32_t*>(&l01), *reinterpret_cast<uint32_t*>(&l23));
        }
    }

    // per-lane ldmatrix address components
    const uint32_t aRow0 = sb + A_HI_OFF + (wm * 32 + (lane & 15)) * 272 + (lane >> 4) * 16;
    const uint32_t aRow1 = aRow0 + 16 * 272;
    const uint32_t bRowB = sb + B_HI_OFF
        + (wn * 64 + (lane & 7) + (lane >> 4) * 8) * 272 + ((lane >> 3) & 1) * 16;
    const uint32_t ALO_D = A_LO_OFF - A_HI_OFF;   // pass-2 A offset
    const uint32_t BLO_D = B_LO_OFF - B_HI_OFF;   // pass-1 B offset

    for (int nt = 0; nt < 3; nt++) {
        __syncthreads();   // previous N-tile's MMAs done -> B smem reusable
        // ---- B tile: rows nt*128..+127 of WT hi/lo ----
        {
            const int row  = tid >> 1;
            const int half = tid & 1;
            const __nv_bfloat16* srcH = &g_wthi[(nt * 128 + row) * 128 + half * 64];
            const __nv_bfloat16* srcL = &g_wtlo[(nt * 128 + row) * 128 + half * 64];
            char* Bhi = smc + B_HI_OFF + row * 272 + half * 128;
            char* Blo = smc + B_LO_OFF + row * 272 + half * 128;
            #pragma unroll
            for (int j = 0; j < 8; j++) {
                *reinterpret_cast<uint4*>(Bhi + j * 16) =
                    *reinterpret_cast<const uint4*>(&srcH[j * 8]);
                *reinterpret_cast<uint4*>(Blo + j * 16) =
                    *reinterpret_cast<const uint4*>(&srcL[j * 8]);
            }
        }
        __syncthreads();

        float d[2][8][4];
        #pragma unroll
        for (int mf = 0; mf < 2; mf++)
            #pragma unroll
            for (int nf = 0; nf < 8; nf++)
                #pragma unroll
                for (int e = 0; e < 4; e++) d[mf][nf][e] = 0.0f;

        #pragma unroll
        for (int pass = 0; pass < 3; pass++) {
            const uint32_t aOff = (pass == 2) ? ALO_D : 0u;
            const uint32_t bOff = (pass == 1) ? BLO_D : 0u;
            #pragma unroll
            for (int k16 = 0; k16 < 8; k16++) {
                uint32_t a0[4], a1[4];
                ldsm4(a0, aRow0 + aOff + k16 * 32);
                ldsm4(a1, aRow1 + aOff + k16 * 32);
                #pragma unroll
                for (int g = 0; g < 4; g++) {
                    uint32_t bb[4];
                    ldsm4(bb, bRowB + bOff + g * (16 * 272) + k16 * 32);
                    mma_bf16(d[0][2 * g],     a0, bb);
                    mma_bf16(d[0][2 * g + 1], a0, bb + 2);
                    mma_bf16(d[1][2 * g],     a1, bb);
                    mma_bf16(d[1][2 * g + 1], a1, bb + 2);
                }
            }
        }

        // ---- epilogue: add bias, store to g_xg / g_xc ----
        {
            const int grp = lane >> 2;
            const int qid = lane & 3;
            #pragma unroll
            for (int nf = 0; nf < 8; nf++) {
                const int cg = wn * 64 + nf * 8 + qid * 2;     // col in N-tile
                float2 bv = *reinterpret_cast<const float2*>(&biasS[nt * 128 + cg]);
                #pragma unroll
                for (int mf = 0; mf < 2; mf++) {
                    const int r0 = m0 + wm * 32 + mf * 16 + grp;
                    float2 v0 = make_float2(d[mf][nf][0] + bv.x, d[mf][nf][1] + bv.y);
                    float2 v1 = make_float2(d[mf][nf][2] + bv.x, d[mf][nf][3] + bv.y);
                    if (nt < 2) {
                        *reinterpret_cast<float2*>(&g_xg[(size_t)r0 * 256 + nt * 128 + cg]) = v0;
                        *reinterpret_cast<float2*>(&g_xg[(size_t)(r0 + 8) * 256 + nt * 128 + cg]) = v1;
                    } else {
                        *reinterpret_cast<float2*>(&g_xc[(size_t)r0 * 128 + cg]) = v0;
                        *reinterpret_cast<float2*>(&g_xc[(size_t)(r0 + 8) * 128 + cg]) = v1;
                    }
                }
            }
        }
    }
}

// ---------------------------------------------------------------------------
// Kernel 2: recurrent scan (unchanged from R9 — passing at 2.27ms).
// ---------------------------------------------------------------------------
__global__ void __launch_bounds__(512, 1) rec_kernel(
    const float* __restrict__ att,
    const float* __restrict__ gk,
    const float* __restrict__ ck,
    const int*   __restrict__ seqlen,
    float* __restrict__ out)
{
    extern __shared__ float sm[];
    float* Wg    = sm;                 // [256][128] swizzled, 128 KB
    float* Wc    = Wg + 32768;         // [128][128] swizzled,  64 KB
    float* stage = Wc + 16384;         // 2 x 128 x 20 = 5120
    float* hT    = stage + 5120;       // interleaved, 1040
    float* rhT   = hT + 1040;
    float* uT    = rhT + 1040;
    float* aS    = uT + 1040;          // 8
    int*   lenS  = reinterpret_cast<int*>(aS + 8);

    const int tid = threadIdx.x;
    const int b0  = blockIdx.x * 8;

    for (int idx = tid; idx < 32768; idx += 512) {
        int k = idx >> 8, j = idx & 255;
        int ph = k ^ ((j & 31) << 2) ^ (((k >> 5) & 1) << 4);
        Wg[j * 128 + ph] = gk[(128 + k) * 256 + j];
    }
    for (int idx = tid; idx < 16384; idx += 512) {
        int k = idx >> 7, j = idx & 127;
        int ph = k ^ ((j & 31) << 2) ^ (((k >> 5) & 1) << 4);
        Wc[j * 128 + ph] = ck[(128 + k) * 128 + j];
    }
    for (int idx = tid; idx < 1040; idx += 512) hT[idx] = 0.0f;
    if (tid < 8) lenS[tid] = seqlen[b0 + tid];
    __syncthreads();

    int tmax = 0;
    #pragma unroll
    for (int i = 0; i < 8; i++) tmax = max(tmax, lenS[i]);

    const int klo = tid & 1;
    const int p   = (tid >> 1) & 127;
    const int khi = tid >> 8;
    const int kbase = khi * 64 + klo * 32;
    const int kx  = kbase ^ (((p & 31) << 2) ^ (klo << 4));
    const float* w0 = Wg + p * 128;
    const float* w1 = w0 + 16384;
    const float* wc = Wc + p * 128;
    const int hoff = kbase * 8 + (2 * khi + klo) * 4;
    float* stp = stage + khi * 2560 + p * 20;

    const int pg = tid >> 2;
    const int q  = tid & 3;
    const int hp2 = pg * 8 + (pg >> 5) * 4 + 2 * q;
    const float* stg_r = stage + pg * 20 + 2 * q;

    for (int t = 0; t < tmax; t++) {
        size_t mrow = ((size_t)(b0 + 2 * q) * TT + t);
        float xgr0 = g_xg[mrow * 256 + pg];
        float xgr1 = g_xg[(mrow + TT) * 256 + pg];
        float xgu0 = g_xg[mrow * 256 + pg + 128];
        float xgu1 = g_xg[(mrow + TT) * 256 + pg + 128];
        float xc0  = g_xc[mrow * 128 + pg];
        float xc1  = g_xc[(mrow + TT) * 128 + pg];
        if (tid < 8) aS[tid] = att[(b0 + tid) * TT + t];

        float2 ar[4], au[4];
        #pragma unroll
        for (int m = 0; m < 4; m++) { ar[m] = make_float2(0.f, 0.f); au[m] = make_float2(0.f, 0.f); }
        {
            const float* hb = hT + hoff;
            #pragma unroll
            for (int kt = 0; kt < 32; kt += 4) {
                int ks = kt ^ kx;
                float4 wr = *reinterpret_cast<const float4*>(w0 + ks);
                float4 wu = *reinterpret_cast<const float4*>(w1 + ks);
                const float wra[4] = {wr.x, wr.y, wr.z, wr.w};
                const float wua[4] = {wu.x, wu.y, wu.z, wu.w};
                #pragma unroll
                for (int jj = 0; jj < 4; jj++) {
                    float4 h03 = *reinterpret_cast<const float4*>(hb + (kt + jj) * 8);
                    float4 h47 = *reinterpret_cast<const float4*>(hb + (kt + jj) * 8 + 4);
                    float2 wr2 = make_float2(wra[jj], wra[jj]);
                    float2 wu2 = make_float2(wua[jj], wua[jj]);
                    ar[0] = ffma2(make_float2(h03.x, h03.y), wr2, ar[0]);
                    ar[1] = ffma2(make_float2(h03.z, h03.w), wr2, ar[1]);
                    ar[2] = ffma2(make_float2(h47.x, h47.y), wr2, ar[2]);
                    ar[3] = ffma2(make_float2(h47.z, h47.w), wr2, ar[3]);
                    au[0] = ffma2(make_float2(h03.x, h03.y), wu2, au[0]);
                    au[1] = ffma2(make_float2(h03.z, h03.w), wu2, au[1]);
                    au[2] = ffma2(make_float2(h47.x, h47.y), wu2, au[2]);
                    au[3] = ffma2(make_float2(h47.z, h47.w), wu2, au[3]);
                }
            }
        }
        #pragma unroll
        for (int m = 0; m < 4; m++) { ar[m] = shfl_red2(ar[m]); au[m] = shfl_red2(au[m]); }
        if (klo == 0) {
            *reinterpret_cast<float4*>(stp)      = make_float4(ar[0].x, ar[0].y, ar[1].x, ar[1].y);
            *reinterpret_cast<float4*>(stp + 4)  = make_float4(ar[2].x, ar[2].y, ar[3].x, ar[3].y);
            *reinterpret_cast<float4*>(stp + 8)  = make_float4(au[0].x, au[0].y, au[1].x, au[1].y);
            *reinterpret_cast<float4*>(stp + 12) = make_float4(au[2].x, au[2].y, au[3].x, au[3].y);
        }
        __syncthreads();

        {
            float2 va = *reinterpret_cast<const float2*>(stg_r);
            float2 vb = *reinterpret_cast<const float2*>(stg_r + 2560);
            float2 wa = *reinterpret_cast<const float2*>(stg_r + 8);
            float2 wb = *reinterpret_cast<const float2*>(stg_r + 2568);
            float r0 = fsigmoid(va.x + vb.x + xgr0);
            float r1 = fsigmoid(va.y + vb.y + xgr1);
            float u0 = fsigmoid(wa.x + wb.x + xgu0);
            float u1 = fsigmoid(wa.y + wb.y + xgu1);
            float2 h2 = *reinterpret_cast<const float2*>(hT + hp2);
            *reinterpret_cast<float2*>(rhT + hp2) = make_float2(r0 * h2.x, r1 * h2.y);
            *reinterpret_cast<float2*>(uT + hp2)  = make_float2(u0, u1);
        }
        __syncthreads();

        float2 ac[4];
        #pragma unroll
        for (int m = 0; m < 4; m++) ac[m] = make_float2(0.f, 0.f);
        {
            const float* rb = rhT + hoff;
            #pragma unroll
            for (int kt = 0; kt < 32; kt += 4) {
                int ks = kt ^ kx;
                float4 wv = *reinterpret_cast<const float4*>(wc + ks);
                const float wca[4] = {wv.x, wv.y, wv.z, wv.w};
                #pragma unroll
                for (int jj = 0; jj < 4; jj++) {
                    float4 r03 = *reinterpret_cast<const float4*>(rb + (kt + jj) * 8);
                    float4 r47 = *reinterpret_cast<const float4*>(rb + (kt + jj) * 8 + 4);
                    float2 w2 = make_float2(wca[jj], wca[jj]);
                    ac[0] = ffma2(make_float2(r03.x, r03.y), w2, ac[0]);
                    ac[1] = ffma2(make_float2(r03.z, r03.w), w2, ac[1]);
                    ac[2] = ffma2(make_float2(r47.x, r47.y), w2, ac[2]);
                    ac[3] = ffma2(make_float2(r47.z, r47.w), w2, ac[3]);
                }
            }
        }
        #pragma unroll
        for (int m = 0; m < 4; m++) ac[m] = shfl_red2(ac[m]);
        if (klo == 0) {
            *reinterpret_cast<float4*>(stp)     = make_float4(ac[0].x, ac[0].y, ac[1].x, ac[1].y);
            *reinterpret_cast<float4*>(stp + 4) = make_float4(ac[2].x, ac[2].y, ac[3].x, ac[3].y);
        }
        __syncthreads();

        {
            float2 ca = *reinterpret_cast<const float2*>(stg_r);
            float2 cb2 = *reinterpret_cast<const float2*>(stg_r + 2560);
            float c0 = tanhf(ca.x + cb2.x + xc0);
            float c1 = tanhf(ca.y + cb2.y + xc1);
            float a0 = aS[2 * q], a1 = aS[2 * q + 1];
            int   l0 = lenS[2 * q], l1 = lenS[2 * q + 1];
            float2 u2 = *reinterpret_cast<const float2*>(uT + hp2);
            float2 h2 = *reinterpret_cast<const float2*>(hT + hp2);
            float uu0 = (1.0f - a0) * u2.x;
            float uu1 = (1.0f - a1) * u2.y;
            float n0 = uu0 * h2.x + (1.0f - uu0) * c0;
            float n1 = uu1 * h2.y + (1.0f - uu1) * c1;
            bool m0 = (t < l0), m1 = (t < l1);
            out[mrow * 128 + pg]        = m0 ? n0 : 0.0f;
            out[(mrow + TT) * 128 + pg] = m1 ? n1 : 0.0f;
            hT[hp2]     = m0 ? n0 : h2.x;
            hT[hp2 + 1] = m1 ? n1 : h2.y;
        }
        __syncthreads();
    }

    for (int t = tmax; t < TT; t++) {
        for (int idx = tid; idx < 1024; idx += 512) {
            int i = idx >> 7, d = idx & 127;
            out[((size_t)(b0 + i) * TT + t) * 128 + d] = 0.0f;
        }
    }
}

// ---------------------------------------------------------------------------
extern "C" void kernel_launch(void* const* d_in, const int* in_sizes, int n_in,
                              void* d_out, int out_size) {
    const float* x   = (const float*)d_in[0];   // rnn_input [B,T,D]
    const float* att = (const float*)d_in[1];   // att_score [B,T,1]
    const float* gk  = (const float*)d_in[2];   // gate_kernel [2D,2D]
    const float* gb  = (const float*)d_in[3];   // gate_bias [2D]
    const float* ck  = (const float*)d_in[4];   // cand_kernel [2D,D]
    const float* cb  = (const float*)d_in[5];   // cand_bias [D]
    const int*   sl  = (const int*)d_in[6];     // sequence_length [B,1]
    float* out = (float*)d_out;                 // [B,T,D]

    const size_t rsmem = (32768 + 16384 + 5120 + 3 * 1040 + 8) * sizeof(float) + 8 * sizeof(int);
    cudaFuncSetAttribute(rec_kernel, cudaFuncAttributeMaxDynamicSharedMemorySize, (int)rsmem);
    cudaFuncSetAttribute(pre_mma, cudaFuncAttributeMaxDynamicSharedMemorySize, PRE_SMEM);

    prep_w<<<384, 128>>>(gk, ck);
    pre_mma<<<(BB * TT) / 128, 256, PRE_SMEM>>>(x, gb, cb);
    rec_kernel<<<BB / 8, 512, rsmem>>>(att, gk, ck, sl, out);
}

// round 13
// speedup vs baseline: 1.9614x; 1.5539x over previous
#include <cuda_runtime.h>
#include <cuda_bf16.h>
#include <cstdint>

// Problem constants
#define BB 1024
#define TT 512
#define DD 128

// Scratch (legal: __device__ globals).
static __device__ float g_xg[134217728];  // B*T*256 : x@Wg_x + gate_bias
static __device__ float g_xc[67108864];   // B*T*128 : x@Wc_x + cand_bias
// x-side W transposed [384][128] K-major, bf16 hi/lo (for pre_mma)
static __device__ __nv_bfloat16 g_wthi[49152];
static __device__ __nv_bfloat16 g_wtlo[49152];
// h-side W transposed [384][128] K-major, bf16 hi/lo (for rec HMMA)
static __device__ __nv_bfloat16 g_whhi[49152];
static __device__ __nv_bfloat16 g_whlo[49152];

// ---------------- helpers ----------------
__device__ __forceinline__ uint32_t smem_u32(const void* p) {
    uint32_t a;
    asm("{ .reg .u64 t; cvta.to.shared.u64 t, %1; cvt.u32.u64 %0, t; }" : "=r"(a) : "l"(p));
    return a;
}
__device__ __forceinline__ void ldsm4(uint32_t* r, uint32_t addr) {
    asm volatile("ldmatrix.sync.aligned.m8n8.x4.shared.b16 {%0,%1,%2,%3}, [%4];"
                 : "=r"(r[0]), "=r"(r[1]), "=r"(r[2]), "=r"(r[3]) : "r"(addr));
}
__device__ __forceinline__ void ldsm2(uint32_t* r, uint32_t addr) {
    asm volatile("ldmatrix.sync.aligned.m8n8.x2.shared.b16 {%0,%1}, [%2];"
                 : "=r"(r[0]), "=r"(r[1]) : "r"(addr));
}
__device__ __forceinline__ void mma_bf16(float* d, const uint32_t* a, const uint32_t* b) {
    asm volatile(
        "mma.sync.aligned.m16n8k16.row.col.f32.bf16.bf16.f32 "
        "{%0,%1,%2,%3}, {%4,%5,%6,%7}, {%8,%9}, {%0,%1,%2,%3};"
        : "+f"(d[0]), "+f"(d[1]), "+f"(d[2]), "+f"(d[3])
        : "r"(a[0]), "r"(a[1]), "r"(a[2]), "r"(a[3]), "r"(b[0]), "r"(b[1]));
}
// pack two fp32 -> bf16x2 (vHI -> upper half, vLO -> lower half)
__device__ __forceinline__ uint32_t pack_bf2(float vHI, float vLO) {
    uint32_t r;
    asm("cvt.rn.bf16x2.f32 %0, %1, %2;" : "=r"(r) : "f"(vHI), "f"(vLO));
    return r;
}
__device__ __forceinline__ float bflo(uint32_t p) { return __uint_as_float(p << 16); }
__device__ __forceinline__ float bfhi(uint32_t p) { return __uint_as_float(p & 0xFFFF0000u); }

__device__ __forceinline__ float fsigmoid(float x) {
    return __fdividef(1.0f, 1.0f + __expf(-x));
}
__device__ __forceinline__ float ftanh(float x) {
    x = fminf(20.0f, fmaxf(-20.0f, x));
    float e = __expf(2.0f * x);
    return __fdividef(e - 1.0f, e + 1.0f);
}

// ---------------------------------------------------------------------------
// Prep: transpose both halves of W to [384][128] K-major, bf16 hi/lo split.
// n<256: gate col n; n>=256: cand col n-256. x-side = rows 0..127 of kernels,
// h-side = rows 128..255.
// ---------------------------------------------------------------------------
__global__ void prep_w(const float* __restrict__ gk, const float* __restrict__ ck) {
    int n = blockIdx.x, k = threadIdx.x;
    float vx = (n < 256) ? gk[k * 256 + n] : ck[k * 128 + (n - 256)];
    __nv_bfloat16 hx = __float2bfloat16(vx);
    g_wthi[n * 128 + k] = hx;
    g_wtlo[n * 128 + k] = __float2bfloat16(vx - __bfloat162float(hx));
    float vh = (n < 256) ? gk[(128 + k) * 256 + n] : ck[(128 + k) * 128 + (n - 256)];
    __nv_bfloat16 hh = __float2bfloat16(vh);
    g_whhi[n * 128 + k] = hh;
    g_whlo[n * 128 + k] = __float2bfloat16(vh - __bfloat162float(hh));
}

// ---------------------------------------------------------------------------
// Kernel 1: hoisted x-GEMM on HMMA (unchanged from R12 — passing).
// ---------------------------------------------------------------------------
#define A_HI_OFF 1536
#define A_LO_OFF (A_HI_OFF + 34816)
#define B_HI_OFF (A_LO_OFF + 34816)
#define B_LO_OFF (B_HI_OFF + 34816)
#define PRE_SMEM (B_LO_OFF + 34816)

__global__ void __launch_bounds__(256) pre_mma(
    const float* __restrict__ X,
    const float* __restrict__ gb, const float* __restrict__ cb)
{
    extern __shared__ char smc[];
    const uint32_t sb = smem_u32(smc);
    float* biasS = reinterpret_cast<float*>(smc);
    const int tid  = threadIdx.x;
    const int lane = tid & 31;
    const int wid  = tid >> 5;
    const int wm   = wid & 3;
    const int wn   = wid >> 2;
    const int m0   = blockIdx.x * 128;

    if (tid < 256) biasS[tid] = gb[tid];
    if (tid < 128) biasS[256 + tid] = cb[tid];

    {
        const int row  = tid >> 1;
        const int half = tid & 1;
        const float* xr = &X[(size_t)(m0 + row) * 128 + half * 64];
        char* Ahi = smc + A_HI_OFF + row * 272 + half * 128;
        char* Alo = smc + A_LO_OFF + row * 272 + half * 128;
        #pragma unroll
        for (int j = 0; j < 16; j++) {
            float4 v = *reinterpret_cast<const float4*>(&xr[j * 4]);
            __nv_bfloat162 h01 = __floats2bfloat162_rn(v.x, v.y);
            __nv_bfloat162 h23 = __floats2bfloat162_rn(v.z, v.w);
            __nv_bfloat162 l01 = __floats2bfloat162_rn(v.x - __bfloat162float(h01.x),
                                                       v.y - __bfloat162float(h01.y));
            __nv_bfloat162 l23 = __floats2bfloat162_rn(v.z - __bfloat162float(h23.x),
                                                       v.w - __bfloat162float(h23.y));
            *reinterpret_cast<uint2*>(Ahi + j * 8) =
                make_uint2(*reinterpret_cast<uint32_t*>(&h01), *reinterpret_cast<uint32_t*>(&h23));
            *reinterpret_cast<uint2*>(Alo + j * 8) =
                make_uint2(*reinterpret_cast<uint32_t*>(&l01), *reinterpret_cast<uint32_t*>(&l23));
        }
    }

    const uint32_t aRow0 = sb + A_HI_OFF + (wm * 32 + (lane & 15)) * 272 + (lane >> 4) * 16;
    const uint32_t aRow1 = aRow0 + 16 * 272;
    const uint32_t bRowB = sb + B_HI_OFF
        + (wn * 64 + (lane & 7) + (lane >> 4) * 8) * 272 + ((lane >> 3) & 1) * 16;
    const uint32_t ALO_D = A_LO_OFF - A_HI_OFF;
    const uint32_t BLO_D = B_LO_OFF - B_HI_OFF;

    for (int nt = 0; nt < 3; nt++) {
        __syncthreads();
        {
            const int row  = tid >> 1;
            const int half = tid & 1;
            const __nv_bfloat16* srcH = &g_wthi[(nt * 128 + row) * 128 + half * 64];
            const __nv_bfloat16* srcL = &g_wtlo[(nt * 128 + row) * 128 + half * 64];
            char* Bhi = smc + B_HI_OFF + row * 272 + half * 128;
            char* Blo = smc + B_LO_OFF + row * 272 + half * 128;
            #pragma unroll
            for (int j = 0; j < 8; j++) {
                *reinterpret_cast<uint4*>(Bhi + j * 16) =
                    *reinterpret_cast<const uint4*>(&srcH[j * 8]);
                *reinterpret_cast<uint4*>(Blo + j * 16) =
                    *reinterpret_cast<const uint4*>(&srcL[j * 8]);
            }
        }
        __syncthreads();

        float d[2][8][4];
        #pragma unroll
        for (int mf = 0; mf < 2; mf++)
            #pragma unroll
            for (int nf = 0; nf < 8; nf++)
                #pragma unroll
                for (int e = 0; e < 4; e++) d[mf][nf][e] = 0.0f;

        #pragma unroll
        for (int pass = 0; pass < 3; pass++) {
            const uint32_t aOff = (pass == 2) ? ALO_D : 0u;
            const uint32_t bOff = (pass == 1) ? BLO_D : 0u;
            #pragma unroll
            for (int k16 = 0; k16 < 8; k16++) {
                uint32_t a0[4], a1[4];
                ldsm4(a0, aRow0 + aOff + k16 * 32);
                ldsm4(a1, aRow1 + aOff + k16 * 32);
                #pragma unroll
                for (int g = 0; g < 4; g++) {
                    uint32_t bb[4];
                    ldsm4(bb, bRowB + bOff + g * (16 * 272) + k16 * 32);
                    mma_bf16(d[0][2 * g],     a0, bb);
                    mma_bf16(d[0][2 * g + 1], a0, bb + 2);
                    mma_bf16(d[1][2 * g],     a1, bb);
                    mma_bf16(d[1][2 * g + 1], a1, bb + 2);
                }
            }
        }

        {
            const int grp = lane >> 2;
            const int qid = lane & 3;
            #pragma unroll
            for (int nf = 0; nf < 8; nf++) {
                const int cg = wn * 64 + nf * 8 + qid * 2;
                float2 bv = *reinterpret_cast<const float2*>(&biasS[nt * 128 + cg]);
                #pragma unroll
                for (int mf = 0; mf < 2; mf++) {
                    const int r0 = m0 + wm * 32 + mf * 16 + grp;
                    float2 v0 = make_float2(d[mf][nf][0] + bv.x, d[mf][nf][1] + bv.y);
                    float2 v1 = make_float2(d[mf][nf][2] + bv.x, d[mf][nf][3] + bv.y);
                    if (nt < 2) {
                        *reinterpret_cast<float2*>(&g_xg[(size_t)r0 * 256 + nt * 128 + cg]) = v0;
                        *reinterpret_cast<float2*>(&g_xg[(size_t)(r0 + 8) * 256 + nt * 128 + cg]) = v1;
                    } else {
                        *reinterpret_cast<float2*>(&g_xc[(size_t)r0 * 128 + cg]) = v0;
                        *reinterpret_cast<float2*>(&g_xc[(size_t)(r0 + 8) * 128 + cg]) = v1;
                    }
                }
            }
        }
    }
}

// ---------------------------------------------------------------------------
// Kernel 2: recurrent scan on HMMA. 128 CTAs x 8 rows, 512 threads (16 warps).
// Gate W (hi/lo) fragments persistent in registers; cand W streamed via ldsm.
// h kept fp32 in smem + bf16 hi/lo copies for MMA A-fragments (M=8, a1=a3=0).
// Per step: [gate MMA + sigmoid + r*h split] -> bar -> [cand MMA + tanh +
// attention-gated update + mask + store + h split] -> bar.
// ---------------------------------------------------------------------------
#define WCHI 0
#define WCLO 34816
#define HHI  69632
#define HLO  71808
#define RHHI 73984
#define RHLO 76160
#define HS   78336
#define US   82560
#define ASMO 86784
#define LENO 86816
#define REC_SMEM 86848

__global__ void __launch_bounds__(512, 1) rec_kernel(
    const float* __restrict__ att,
    const int*   __restrict__ seqlen,
    float* __restrict__ out)
{
    extern __shared__ char smc[];
    const uint32_t sb = smem_u32(smc);
    float* hS   = reinterpret_cast<float*>(smc + HS);    // [8][132] fp32
    float* uS   = reinterpret_cast<float*>(smc + US);    // [8][132] fp32
    float* aS   = reinterpret_cast<float*>(smc + ASMO);  // [8]
    int*   lenS = reinterpret_cast<int*>(smc + LENO);    // [8]

    const int tid  = threadIdx.x;
    const int lane = tid & 31;
    const int w    = tid >> 5;
    const int b0   = blockIdx.x * 8;

    // stage cand h-side W hi/lo into smem [128 n][272B rows]
    for (int idx = tid; idx < 8192; idx += 512) {
        int rown = idx >> 6, kp = (idx & 63) * 2;
        *reinterpret_cast<uint32_t*>(smc + WCHI + rown * 272 + kp * 2) =
            *reinterpret_cast<const uint32_t*>(&g_whhi[(256 + rown) * 128 + kp]);
        *reinterpret_cast<uint32_t*>(smc + WCLO + rown * 272 + kp * 2) =
            *reinterpret_cast<const uint32_t*>(&g_whlo[(256 + rown) * 128 + kp]);
    }
    for (int idx = tid; idx < 1056; idx += 512) hS[idx] = 0.0f;
    for (int idx = tid; idx < 544; idx += 512) {
        reinterpret_cast<uint32_t*>(smc + HHI)[idx] = 0u;
        reinterpret_cast<uint32_t*>(smc + HLO)[idx] = 0u;
    }
    if (tid < 8) lenS[tid] = seqlen[b0 + tid];
    __syncthreads();

    int tmax = 0;
    #pragma unroll
    for (int i = 0; i < 8; i++) tmax = max(tmax, lenS[i]);

    const int row  = lane >> 2;        // 0..7 (batch row within CTA)
    const int colp = (lane & 3) * 2;   // col pair base within n-tile
    const int cw   = w * 16;           // gate col base (w<8: r cols, w>=8: u cols)
    const bool isr = (w < 8);
    const int ccol = w * 8 + colp;     // cand col

    // ---- preload gate W fragments (persistent in registers) ----
    uint32_t wgh[2][8][2], wgl[2][8][2];
    #pragma unroll
    for (int nt = 0; nt < 2; nt++)
        #pragma unroll
        for (int kt = 0; kt < 8; kt++) {
            int n = cw + nt * 8 + (lane >> 2);
            int base = n * 128 + kt * 16 + colp;
            wgh[nt][kt][0] = *reinterpret_cast<const uint32_t*>(&g_whhi[base]);
            wgh[nt][kt][1] = *reinterpret_cast<const uint32_t*>(&g_whhi[base + 8]);
            wgl[nt][kt][0] = *reinterpret_cast<const uint32_t*>(&g_whlo[base]);
            wgl[nt][kt][1] = *reinterpret_cast<const uint32_t*>(&g_whlo[base + 8]);
        }

    const uint32_t aAg = sb + HHI  + (lane & 7) * 272 + ((lane >> 3) & 1) * 16;
    const uint32_t aAc = sb + RHHI + (lane & 7) * 272 + ((lane >> 3) & 1) * 16;
    const uint32_t bAc = sb + WCHI + (w * 8 + (lane & 7)) * 272 + ((lane >> 3) & 1) * 16;

    for (int t = 0; t < tmax; t++) {
        const size_t mr = (size_t)(b0 + row) * TT + t;
        // early loads (hidden under gate MMA)
        float2 xg0 = *reinterpret_cast<const float2*>(&g_xg[mr * 256 + cw + colp]);
        float2 xg1 = *reinterpret_cast<const float2*>(&g_xg[mr * 256 + cw + 8 + colp]);
        if (tid < 8) aS[tid] = att[(b0 + tid) * TT + t];

        // ---- gate MMA: 2 n-tiles x 8 k-tiles x 3 passes ----
        float dg[2][4] = {{0.f, 0.f, 0.f, 0.f}, {0.f, 0.f, 0.f, 0.f}};
        #pragma unroll
        for (int kt = 0; kt < 8; kt++) {
            uint32_t ah[2], al[2];
            ldsm2(ah, aAg + kt * 32);
            ldsm2(al, aAg + (HLO - HHI) + kt * 32);
            uint32_t afh[4] = {ah[0], 0u, ah[1], 0u};
            uint32_t afl[4] = {al[0], 0u, al[1], 0u};
            #pragma unroll
            for (int nt = 0; nt < 2; nt++) {
                mma_bf16(dg[nt], afh, wgh[nt][kt]);
                mma_bf16(dg[nt], afh, wgl[nt][kt]);
                mma_bf16(dg[nt], afl, wgh[nt][kt]);
            }
        }
        // ---- gate epilogue ----
        {
            float s0 = fsigmoid(dg[0][0] + xg0.x);
            float s1 = fsigmoid(dg[0][1] + xg0.y);
            float s2 = fsigmoid(dg[1][0] + xg1.x);
            float s3 = fsigmoid(dg[1][1] + xg1.y);
            if (isr) {
                int c0 = cw + colp, c1 = cw + 8 + colp;
                float2 ha = *reinterpret_cast<const float2*>(&hS[row * 132 + c0]);
                float2 hb = *reinterpret_cast<const float2*>(&hS[row * 132 + c1]);
                float r0 = s0 * ha.x, r1 = s1 * ha.y;
                float r2 = s2 * hb.x, r3 = s3 * hb.y;
                uint32_t p0 = pack_bf2(r1, r0);
                uint32_t p1 = pack_bf2(r3, r2);
                uint32_t q0 = pack_bf2(r1 - bfhi(p0), r0 - bflo(p0));
                uint32_t q1 = pack_bf2(r3 - bfhi(p1), r2 - bflo(p1));
                *reinterpret_cast<uint32_t*>(smc + RHHI + row * 272 + c0 * 2) = p0;
                *reinterpret_cast<uint32_t*>(smc + RHHI + row * 272 + c1 * 2) = p1;
                *reinterpret_cast<uint32_t*>(smc + RHLO + row * 272 + c0 * 2) = q0;
                *reinterpret_cast<uint32_t*>(smc + RHLO + row * 272 + c1 * 2) = q1;
            } else {
                int c0 = cw - 128 + colp;
                *reinterpret_cast<float2*>(&uS[row * 132 + c0])     = make_float2(s0, s1);
                *reinterpret_cast<float2*>(&uS[row * 132 + c0 + 8]) = make_float2(s2, s3);
            }
        }
        __syncthreads();

        // ---- cand MMA: 1 n-tile x 8 k-tiles x 3 passes (B streamed) ----
        float2 xc = *reinterpret_cast<const float2*>(&g_xc[mr * 128 + ccol]);
        float dc[4] = {0.f, 0.f, 0.f, 0.f};
        #pragma unroll
        for (int kt = 0; kt < 8; kt++) {
            uint32_t ah[2], al[2], bh[2], bl[2];
            ldsm2(ah, aAc + kt * 32);
            ldsm2(al, aAc + (RHLO - RHHI) + kt * 32);
            ldsm2(bh, bAc + kt * 32);
            ldsm2(bl, bAc + (WCLO - WCHI) + kt * 32);
            uint32_t afh[4] = {ah[0], 0u, ah[1], 0u};
            uint32_t afl[4] = {al[0], 0u, al[1], 0u};
            mma_bf16(dc, afh, bh);
            mma_bf16(dc, afh, bl);
            mma_bf16(dc, afl, bh);
        }
        // ---- cand epilogue: tanh + attention-gated update + mask + store ----
        {
            float c0 = ftanh(dc[0] + xc.x);
            float c1 = ftanh(dc[1] + xc.y);
            float2 u2 = *reinterpret_cast<const float2*>(&uS[row * 132 + ccol]);
            float2 h2 = *reinterpret_cast<const float2*>(&hS[row * 132 + ccol]);
            float a = aS[row];
            int len = lenS[row];
            float uu0 = (1.0f - a) * u2.x;
            float uu1 = (1.0f - a) * u2.y;
            float n0 = uu0 * h2.x + (1.0f - uu0) * c0;
            float n1 = uu1 * h2.y + (1.0f - uu1) * c1;
            bool mk = (t < len);
            *reinterpret_cast<float2*>(&out[mr * 128 + ccol]) =
                mk ? make_float2(n0, n1) : make_float2(0.0f, 0.0f);
            if (mk) {
                *reinterpret_cast<float2*>(&hS[row * 132 + ccol]) = make_float2(n0, n1);
                uint32_t p = pack_bf2(n1, n0);
                uint32_t q = pack_bf2(n1 - bfhi(p), n0 - bflo(p));
                *reinterpret_cast<uint32_t*>(smc + HHI + row * 272 + ccol * 2) = p;
                *reinterpret_cast<uint32_t*>(smc + HLO + row * 272 + ccol * 2) = q;
            }
        }
        __syncthreads();
    }

    // dynamic_rnn zeroes outputs past the sequence length; t >= tmax >= len[i]
    for (int t = tmax; t < TT; t++) {
        for (int idx = tid; idx < 1024; idx += 512) {
            int i = idx >> 7, d = idx & 127;
            out[((size_t)(b0 + i) * TT + t) * 128 + d] = 0.0f;
        }
    }
}

// ---------------------------------------------------------------------------
extern "C" void kernel_launch(void* const* d_in, const int* in_sizes, int n_in,
                              void* d_out, int out_size) {
    const float* x   = (const float*)d_in[0];   // rnn_input [B,T,D]
    const float* att = (const float*)d_in[1];   // att_score [B,T,1]
    const float* gk  = (const float*)d_in[2];   // gate_kernel [2D,2D]
    const float* gb  = (const float*)d_in[3];   // gate_bias [2D]
    const float* ck  = (const float*)d_in[4];   // cand_kernel [2D,D]
    const float* cb  = (const float*)d_in[5];   // cand_bias [D]
    const int*   sl  = (const int*)d_in[6];     // sequence_length [B,1]
    float* out = (float*)d_out;                 // [B,T,D]

    cudaFuncSetAttribute(pre_mma, cudaFuncAttributeMaxDynamicSharedMemorySize, PRE_SMEM);
    cudaFuncSetAttribute(rec_kernel, cudaFuncAttributeMaxDynamicSharedMemorySize, REC_SMEM);

    prep_w<<<384, 128>>>(gk, ck);
    pre_mma<<<(BB * TT) / 128, 256, PRE_SMEM>>>(x, gb, cb);
    rec_kernel<<<BB / 8, 512, REC_SMEM>>>(att, sl, out);
}

// round 14
// speedup vs baseline: 2.1742x; 1.1085x over previous
#include <cuda_runtime.h>
#include <cuda_bf16.h>
#include <cstdint>

// Problem constants
#define BB 1024
#define TT 512
#define DD 128

// Scratch (legal: __device__ globals).
static __device__ float g_xg[134217728];  // B*T*256 : x@Wg_x + gate_bias
static __device__ float g_xc[67108864];   // B*T*128 : x@Wc_x + cand_bias
// x-side W transposed [384][128] K-major, bf16 hi/lo (for pre_mma)
static __device__ __nv_bfloat16 g_wthi[49152];
static __device__ __nv_bfloat16 g_wtlo[49152];
// h-side W transposed [384][128] K-major, bf16 hi/lo (for rec HMMA)
static __device__ __nv_bfloat16 g_whhi[49152];
static __device__ __nv_bfloat16 g_whlo[49152];

// ---------------- helpers ----------------
__device__ __forceinline__ uint32_t smem_u32(const void* p) {
    uint32_t a;
    asm("{ .reg .u64 t; cvta.to.shared.u64 t, %1; cvt.u32.u64 %0, t; }" : "=r"(a) : "l"(p));
    return a;
}
__device__ __forceinline__ void ldsm4(uint32_t* r, uint32_t addr) {
    asm volatile("ldmatrix.sync.aligned.m8n8.x4.shared.b16 {%0,%1,%2,%3}, [%4];"
                 : "=r"(r[0]), "=r"(r[1]), "=r"(r[2]), "=r"(r[3]) : "r"(addr));
}
__device__ __forceinline__ void mma_bf16(float* d, const uint32_t* a, const uint32_t* b) {
    asm volatile(
        "mma.sync.aligned.m16n8k16.row.col.f32.bf16.bf16.f32 "
        "{%0,%1,%2,%3}, {%4,%5,%6,%7}, {%8,%9}, {%0,%1,%2,%3};"
        : "+f"(d[0]), "+f"(d[1]), "+f"(d[2]), "+f"(d[3])
        : "r"(a[0]), "r"(a[1]), "r"(a[2]), "r"(a[3]), "r"(b[0]), "r"(b[1]));
}
__device__ __forceinline__ void cpa16(uint32_t s, const void* g) {
    asm volatile("cp.async.cg.shared.global [%0], [%1], 16;"
                 :: "r"(s), "l"(__cvta_generic_to_global(g)) : "memory");
}
#define CP_COMMIT() asm volatile("cp.async.commit_group;" ::: "memory")
#define CP_WAIT0()  asm volatile("cp.async.wait_group 0;" ::: "memory")

// pack two fp32 -> bf16x2 (vHI -> upper half, vLO -> lower half)
__device__ __forceinline__ uint32_t pack_bf2(float vHI, float vLO) {
    uint32_t r;
    asm("cvt.rn.bf16x2.f32 %0, %1, %2;" : "=r"(r) : "f"(vHI), "f"(vLO));
    return r;
}
__device__ __forceinline__ float bflo(uint32_t p) { return __uint_as_float(p << 16); }
__device__ __forceinline__ float bfhi(uint32_t p) { return __uint_as_float(p & 0xFFFF0000u); }

__device__ __forceinline__ float fsigmoid(float x) {
    return __fdividef(1.0f, 1.0f + __expf(-x));
}
__device__ __forceinline__ float ftanh(float x) {
    x = fminf(20.0f, fmaxf(-20.0f, x));
    float e = __expf(2.0f * x);
    return __fdividef(e - 1.0f, e + 1.0f);
}

// ---------------------------------------------------------------------------
// Prep: transpose both halves of W to [384][128] K-major, bf16 hi/lo split.
// ---------------------------------------------------------------------------
__global__ void prep_w(const float* __restrict__ gk, const float* __restrict__ ck) {
    int n = blockIdx.x, k = threadIdx.x;
    float vx = (n < 256) ? gk[k * 256 + n] : ck[k * 128 + (n - 256)];
    __nv_bfloat16 hx = __float2bfloat16(vx);
    g_wthi[n * 128 + k] = hx;
    g_wtlo[n * 128 + k] = __float2bfloat16(vx - __bfloat162float(hx));
    float vh = (n < 256) ? gk[(128 + k) * 256 + n] : ck[(128 + k) * 128 + (n - 256)];
    __nv_bfloat16 hh = __float2bfloat16(vh);
    g_whhi[n * 128 + k] = hh;
    g_whlo[n * 128 + k] = __float2bfloat16(vh - __bfloat162float(hh));
}

// ---------------------------------------------------------------------------
// Kernel 1: hoisted x-GEMM on HMMA, bf16x3 split, cp.async double-buffered B.
// smem: bias[384f] | Ahi 128x272 | Alo | Bbuf0(hi,lo) | Bbuf1(hi,lo)
// ---------------------------------------------------------------------------
#define A_HI_OFF 1536
#define A_LO_OFF (A_HI_OFF + 34816)
#define B_BUF0   (A_LO_OFF + 34816)
#define B_BUF1   (B_BUF0 + 69632)
#define PRE_SMEM (B_BUF1 + 69632)

__global__ void __launch_bounds__(256) pre_mma(
    const float* __restrict__ X,
    const float* __restrict__ gb, const float* __restrict__ cb)
{
    extern __shared__ char smc[];
    const uint32_t sb = smem_u32(smc);
    float* biasS = reinterpret_cast<float*>(smc);
    const int tid  = threadIdx.x;
    const int lane = tid & 31;
    const int wid  = tid >> 5;
    const int wm   = wid & 3;
    const int wn   = wid >> 2;
    const int m0   = blockIdx.x * 128;

    if (tid < 256) biasS[tid] = gb[tid];
    if (tid < 128) biasS[256 + tid] = cb[tid];

    // ---- issue B tile nt=0 via cp.async (row,half per thread-pair) ----
    {
        const int row  = tid >> 1;
        const int half = tid & 1;
        uint32_t dHi = sb + B_BUF0 + row * 272 + half * 128;
        uint32_t dLo = dHi + 34816;
        const __nv_bfloat16* sH = &g_wthi[row * 128 + half * 64];
        const __nv_bfloat16* sL = &g_wtlo[row * 128 + half * 64];
        #pragma unroll
        for (int j = 0; j < 8; j++) {
            cpa16(dHi + j * 16, sH + j * 8);
            cpa16(dLo + j * 16, sL + j * 8);
        }
        CP_COMMIT();
    }

    // ---- A tile: fp32 -> bf16 hi/lo, padded rows (272B) ----
    {
        const int row  = tid >> 1;
        const int half = tid & 1;
        const float* xr = &X[(size_t)(m0 + row) * 128 + half * 64];
        char* Ahi = smc + A_HI_OFF + row * 272 + half * 128;
        char* Alo = smc + A_LO_OFF + row * 272 + half * 128;
        #pragma unroll
        for (int j = 0; j < 16; j++) {
            float4 v = *reinterpret_cast<const float4*>(&xr[j * 4]);
            __nv_bfloat162 h01 = __floats2bfloat162_rn(v.x, v.y);
            __nv_bfloat162 h23 = __floats2bfloat162_rn(v.z, v.w);
            __nv_bfloat162 l01 = __floats2bfloat162_rn(v.x - __bfloat162float(h01.x),
                                                       v.y - __bfloat162float(h01.y));
            __nv_bfloat162 l23 = __floats2bfloat162_rn(v.z - __bfloat162float(h23.x),
                                                       v.w - __bfloat162float(h23.y));
            *reinterpret_cast<uint2*>(Ahi + j * 8) =
                make_uint2(*reinterpret_cast<uint32_t*>(&h01), *reinterpret_cast<uint32_t*>(&h23));
            *reinterpret_cast<uint2*>(Alo + j * 8) =
                make_uint2(*reinterpret_cast<uint32_t*>(&l01), *reinterpret_cast<uint32_t*>(&l23));
        }
    }

    const uint32_t aRow0 = sb + A_HI_OFF + (wm * 32 + (lane & 15)) * 272 + (lane >> 4) * 16;
    const uint32_t aRow1 = aRow0 + 16 * 272;
    const uint32_t ALO_D = A_LO_OFF - A_HI_OFF;

    for (int nt = 0; nt < 3; nt++) {
        CP_WAIT0();
        __syncthreads();
        const uint32_t bufC = (nt & 1) ? B_BUF1 : B_BUF0;
        // issue next B tile into the other buffer (overlaps MMA below)
        if (nt < 2) {
            const int row  = tid >> 1;
            const int half = tid & 1;
            const uint32_t bufN = (nt & 1) ? B_BUF0 : B_BUF1;
            uint32_t dHi = sb + bufN + row * 272 + half * 128;
            uint32_t dLo = dHi + 34816;
            const __nv_bfloat16* sH = &g_wthi[((nt + 1) * 128 + row) * 128 + half * 64];
            const __nv_bfloat16* sL = &g_wtlo[((nt + 1) * 128 + row) * 128 + half * 64];
            #pragma unroll
            for (int j = 0; j < 8; j++) {
                cpa16(dHi + j * 16, sH + j * 8);
                cpa16(dLo + j * 16, sL + j * 8);
            }
            CP_COMMIT();
        }

        const uint32_t bRowB = sb + bufC
            + (wn * 64 + (lane & 7) + (lane >> 4) * 8) * 272 + ((lane >> 3) & 1) * 16;

        float d[2][8][4];
        #pragma unroll
        for (int mf = 0; mf < 2; mf++)
            #pragma unroll
            for (int nf = 0; nf < 8; nf++)
                #pragma unroll
                for (int e = 0; e < 4; e++) d[mf][nf][e] = 0.0f;

        #pragma unroll
        for (int pass = 0; pass < 3; pass++) {
            const uint32_t aOff = (pass == 2) ? ALO_D : 0u;
            const uint32_t bOff = (pass == 1) ? 34816u : 0u;
            #pragma unroll
            for (int k16 = 0; k16 < 8; k16++) {
                uint32_t a0[4], a1[4];
                ldsm4(a0, aRow0 + aOff + k16 * 32);
                ldsm4(a1, aRow1 + aOff + k16 * 32);
                #pragma unroll
                for (int g = 0; g < 4; g++) {
                    uint32_t bb[4];
                    ldsm4(bb, bRowB + bOff + g * (16 * 272) + k16 * 32);
                    mma_bf16(d[0][2 * g],     a0, bb);
                    mma_bf16(d[0][2 * g + 1], a0, bb + 2);
                    mma_bf16(d[1][2 * g],     a1, bb);
                    mma_bf16(d[1][2 * g + 1], a1, bb + 2);
                }
            }
        }

        {
            const int grp = lane >> 2;
            const int qid = lane & 3;
            #pragma unroll
            for (int nf = 0; nf < 8; nf++) {
                const int cg = wn * 64 + nf * 8 + qid * 2;
                float2 bv = *reinterpret_cast<const float2*>(&biasS[nt * 128 + cg]);
                #pragma unroll
                for (int mf = 0; mf < 2; mf++) {
                    const int r0 = m0 + wm * 32 + mf * 16 + grp;
                    float2 v0 = make_float2(d[mf][nf][0] + bv.x, d[mf][nf][1] + bv.y);
                    float2 v1 = make_float2(d[mf][nf][2] + bv.x, d[mf][nf][3] + bv.y);
                    if (nt < 2) {
                        *reinterpret_cast<float2*>(&g_xg[(size_t)r0 * 256 + nt * 128 + cg]) = v0;
                        *reinterpret_cast<float2*>(&g_xg[(size_t)(r0 + 8) * 256 + nt * 128 + cg]) = v1;
                    } else {
                        *reinterpret_cast<float2*>(&g_xc[(size_t)r0 * 128 + cg]) = v0;
                        *reinterpret_cast<float2*>(&g_xc[(size_t)(r0 + 8) * 128 + cg]) = v1;
                    }
                }
            }
        }
    }
}

// ---------------------------------------------------------------------------
// Kernel 2: recurrent scan on HMMA. 128 CTAs x 8 rows, 512 threads (16 warps).
// Gate W persistent in registers; cand W streamed via ldsm.x4 (hi+lo fused).
// xg/xc loads software-pipelined one step ahead; att preloaded to smem.
// ---------------------------------------------------------------------------
#define WCHI 0
#define WCLO 34816
#define HHI  69632
#define HLO  71808
#define RHHI 73984
#define RHLO 76160
#define HS   78336
#define US   82560
#define ATTS 86784
#define LENO 103168
#define REC_SMEM 103200

__global__ void __launch_bounds__(512, 1) rec_kernel(
    const float* __restrict__ att,
    const int*   __restrict__ seqlen,
    float* __restrict__ out)
{
    extern __shared__ char smc[];
    const uint32_t sb = smem_u32(smc);
    float* hS   = reinterpret_cast<float*>(smc + HS);    // [8][132] fp32
    float* uS   = reinterpret_cast<float*>(smc + US);    // [8][132] fp32
    float* attS = reinterpret_cast<float*>(smc + ATTS);  // [8][512]
    int*   lenS = reinterpret_cast<int*>(smc + LENO);    // [8]

    const int tid  = threadIdx.x;
    const int lane = tid & 31;
    const int w    = tid >> 5;
    const int b0   = blockIdx.x * 8;

    // stage cand h-side W hi/lo into smem [128 n][272B rows]
    for (int idx = tid; idx < 8192; idx += 512) {
        int rown = idx >> 6, kp = (idx & 63) * 2;
        *reinterpret_cast<uint32_t*>(smc + WCHI + rown * 272 + kp * 2) =
            *reinterpret_cast<const uint32_t*>(&g_whhi[(256 + rown) * 128 + kp]);
        *reinterpret_cast<uint32_t*>(smc + WCLO + rown * 272 + kp * 2) =
            *reinterpret_cast<const uint32_t*>(&g_whlo[(256 + rown) * 128 + kp]);
    }
    // att preload: attS[i][t]
    for (int idx = tid; idx < 4096; idx += 512) {
        int i = idx >> 9, t = idx & 511;
        attS[idx] = att[(b0 + i) * TT + t];
    }
    for (int idx = tid; idx < 1056; idx += 512) hS[idx] = 0.0f;
    for (int idx = tid; idx < 544; idx += 512) {
        reinterpret_cast<uint32_t*>(smc + HHI)[idx] = 0u;
        reinterpret_cast<uint32_t*>(smc + HLO)[idx] = 0u;
    }
    if (tid < 8) lenS[tid] = seqlen[b0 + tid];
    __syncthreads();

    int tmax = 0;
    #pragma unroll
    for (int i = 0; i < 8; i++) tmax = max(tmax, lenS[i]);

    const int row  = lane >> 2;        // 0..7 (batch row within CTA)
    const int colp = (lane & 3) * 2;   // col pair base within n-tile
    const int cw   = w * 16;           // gate col base (w<8: r cols, w>=8: u cols)
    const bool isr = (w < 8);
    const int ccol = w * 8 + colp;     // cand col

    // ---- preload gate W fragments (persistent in registers) ----
    uint32_t wgh[2][8][2], wgl[2][8][2];
    #pragma unroll
    for (int nt = 0; nt < 2; nt++)
        #pragma unroll
        for (int kt = 0; kt < 8; kt++) {
            int n = cw + nt * 8 + (lane >> 2);
            int base = n * 128 + kt * 16 + colp;
            wgh[nt][kt][0] = *reinterpret_cast<const uint32_t*>(&g_whhi[base]);
            wgh[nt][kt][1] = *reinterpret_cast<const uint32_t*>(&g_whhi[base + 8]);
            wgl[nt][kt][0] = *reinterpret_cast<const uint32_t*>(&g_whlo[base]);
            wgl[nt][kt][1] = *reinterpret_cast<const uint32_t*>(&g_whlo[base + 8]);
        }

    // fused hi/lo ldsm.x4 bases: matrices {0,1}=hi, {2,3}=lo
    const uint32_t laneRH = (lane & 7) * 272 + ((lane >> 3) & 1) * 16;
    const uint32_t aAg4 = sb + (lane < 16 ? HHI  : HLO)  + laneRH;
    const uint32_t aAc4 = sb + (lane < 16 ? RHHI : RHLO) + laneRH;
    const uint32_t bAc4 = sb + (lane < 16 ? WCHI : WCLO)
        + (w * 8 + (lane & 7)) * 272 + ((lane >> 3) & 1) * 16;

    const size_t mrB = (size_t)(b0 + row) * TT;
    // pipeline: loads for step t issued at top of step t-1 (here: t=0 preload)
    float2 nxg0 = *reinterpret_cast<const float2*>(&g_xg[mrB * 256 + cw + colp]);
    float2 nxg1 = *reinterpret_cast<const float2*>(&g_xg[mrB * 256 + cw + 8 + colp]);
    float2 nxc  = *reinterpret_cast<const float2*>(&g_xc[mrB * 128 + ccol]);

    for (int t = 0; t < tmax; t++) {
        const float2 xg0 = nxg0, xg1 = nxg1, xc = nxc;
        {   // issue next step's loads (hidden under this whole step)
            const int tn = (t + 1 < tmax) ? t + 1 : t;
            nxg0 = *reinterpret_cast<const float2*>(&g_xg[(mrB + tn) * 256 + cw + colp]);
            nxg1 = *reinterpret_cast<const float2*>(&g_xg[(mrB + tn) * 256 + cw + 8 + colp]);
            nxc  = *reinterpret_cast<const float2*>(&g_xc[(mrB + tn) * 128 + ccol]);
        }

        // ---- gate MMA: 2 n-tiles x 8 k-tiles x 3 passes ----
        float dg[2][4] = {{0.f, 0.f, 0.f, 0.f}, {0.f, 0.f, 0.f, 0.f}};
        #pragma unroll
        for (int kt = 0; kt < 8; kt++) {
            uint32_t g4[4];
            ldsm4(g4, aAg4 + kt * 32);
            uint32_t afh[4] = {g4[0], 0u, g4[1], 0u};
            uint32_t afl[4] = {g4[2], 0u, g4[3], 0u};
            #pragma unroll
            for (int nt = 0; nt < 2; nt++) {
                mma_bf16(dg[nt], afh, wgh[nt][kt]);
                mma_bf16(dg[nt], afh, wgl[nt][kt]);
                mma_bf16(dg[nt], afl, wgh[nt][kt]);
            }
        }
        // ---- gate epilogue ----
        {
            float s0 = fsigmoid(dg[0][0] + xg0.x);
            float s1 = fsigmoid(dg[0][1] + xg0.y);
            float s2 = fsigmoid(dg[1][0] + xg1.x);
            float s3 = fsigmoid(dg[1][1] + xg1.y);
            if (isr) {
                int c0 = cw + colp, c1 = cw + 8 + colp;
                float2 ha = *reinterpret_cast<const float2*>(&hS[row * 132 + c0]);
                float2 hb = *reinterpret_cast<const float2*>(&hS[row * 132 + c1]);
                float r0 = s0 * ha.x, r1 = s1 * ha.y;
                float r2 = s2 * hb.x, r3 = s3 * hb.y;
                uint32_t p0 = pack_bf2(r1, r0);
                uint32_t p1 = pack_bf2(r3, r2);
                uint32_t q0 = pack_bf2(r1 - bfhi(p0), r0 - bflo(p0));
                uint32_t q1 = pack_bf2(r3 - bfhi(p1), r2 - bflo(p1));
                *reinterpret_cast<uint32_t*>(smc + RHHI + row * 272 + c0 * 2) = p0;
                *reinterpret_cast<uint32_t*>(smc + RHHI + row * 272 + c1 * 2) = p1;
                *reinterpret_cast<uint32_t*>(smc + RHLO + row * 272 + c0 * 2) = q0;
                *reinterpret_cast<uint32_t*>(smc + RHLO + row * 272 + c1 * 2) = q1;
            } else {
                int c0 = cw - 128 + colp;
                *reinterpret_cast<float2*>(&uS[row * 132 + c0])     = make_float2(s0, s1);
                *reinterpret_cast<float2*>(&uS[row * 132 + c0 + 8]) = make_float2(s2, s3);
            }
        }
        __syncthreads();

        // ---- cand MMA: 1 n-tile x 8 k-tiles x 3 passes ----
        float dc[4] = {0.f, 0.f, 0.f, 0.f};
        #pragma unroll
        for (int kt = 0; kt < 8; kt++) {
            uint32_t a4[4], b4[4];
            ldsm4(a4, aAc4 + kt * 32);
            ldsm4(b4, bAc4 + kt * 32);
            uint32_t afh[4] = {a4[0], 0u, a4[1], 0u};
            uint32_t afl[4] = {a4[2], 0u, a4[3], 0u};
            mma_bf16(dc, afh, b4);       // hi*hi
            mma_bf16(dc, afh, b4 + 2);   // hi*lo
            mma_bf16(dc, afl, b4);       // lo*hi
        }
        // ---- cand epilogue: tanh + attention-gated update + mask + store ----
        {
            float c0 = ftanh(dc[0] + xc.x);
            float c1 = ftanh(dc[1] + xc.y);
            float2 u2 = *reinterpret_cast<const float2*>(&uS[row * 132 + ccol]);
            float2 h2 = *reinterpret_cast<const float2*>(&hS[row * 132 + ccol]);
            float a = attS[row * 512 + t];
            int len = lenS[row];
            float uu0 = (1.0f - a) * u2.x;
            float uu1 = (1.0f - a) * u2.y;
            float n0 = uu0 * h2.x + (1.0f - uu0) * c0;
            float n1 = uu1 * h2.y + (1.0f - uu1) * c1;
            bool mk = (t < len);
            *reinterpret_cast<float2*>(&out[(mrB + t) * 128 + ccol]) =
                mk ? make_float2(n0, n1) : make_float2(0.0f, 0.0f);
            if (mk) {
                *reinterpret_cast<float2*>(&hS[row * 132 + ccol]) = make_float2(n0, n1);
                uint32_t p = pack_bf2(n1, n0);
                uint32_t q = pack_bf2(n1 - bfhi(p), n0 - bflo(p));
                *reinterpret_cast<uint32_t*>(smc + HHI + row * 272 + ccol * 2) = p;
                *reinterpret_cast<uint32_t*>(smc + HLO + row * 272 + ccol * 2) = q;
            }
        }
        __syncthreads();
    }

    // dynamic_rnn zeroes outputs past the sequence length; t >= tmax >= len[i]
    for (int t = tmax; t < TT; t++) {
        for (int idx = tid; idx < 1024; idx += 512) {
            int i = idx >> 7, d = idx & 127;
            out[((size_t)(b0 + i) * TT + t) * 128 + d] = 0.0f;
        }
    }
}

// ---------------------------------------------------------------------------
extern "C" void kernel_launch(void* const* d_in, const int* in_sizes, int n_in,
                              void* d_out, int out_size) {
    const float* x   = (const float*)d_in[0];   // rnn_input [B,T,D]
    const float* att = (const float*)d_in[1];   // att_score [B,T,1]
    const float* gk  = (const float*)d_in[2];   // gate_kernel [2D,2D]
    const float* gb  = (const float*)d_in[3];   // gate_bias [2D]
    const float* ck  = (const float*)d_in[4];   // cand_kernel [2D,D]
    const float* cb  = (const float*)d_in[5];   // cand_bias [D]
    const int*   sl  = (const int*)d_in[6];     // sequence_length [B,1]
    float* out = (float*)d_out;                 // [B,T,D]

    cudaFuncSetAttribute(pre_mma, cudaFuncAttributeMaxDynamicSharedMemorySize, PRE_SMEM);
    cudaFuncSetAttribute(rec_kernel, cudaFuncAttributeMaxDynamicSharedMemorySize, REC_SMEM);

    prep_w<<<384, 128>>>(gk, ck);
    pre_mma<<<(BB * TT) / 128, 256, PRE_SMEM>>>(x, gb, cb);
    rec_kernel<<<BB / 8, 512, REC_SMEM>>>(att, sl, out);
}

// round 15
// speedup vs baseline: 2.4451x; 1.1246x over previous
#include <cuda_runtime.h>
#include <cuda_bf16.h>
#include <cstdint>

// Problem constants
#define BB 1024
#define TT 512
#define DD 128

// Scratch (legal: __device__ globals).
static __device__ float g_xg[134217728];  // B*T*256 : x@Wg_x + gate_bias
static __device__ float g_xc[67108864];   // B*T*128 : x@Wc_x + cand_bias
// x-side W transposed [384][128] K-major, bf16 hi/lo (for pre_mma)
static __device__ __nv_bfloat16 g_wthi[49152];
static __device__ __nv_bfloat16 g_wtlo[49152];
// h-side W transposed [384][128] K-major, bf16 hi/lo (for rec HMMA)
static __device__ __nv_bfloat16 g_whhi[49152];
static __device__ __nv_bfloat16 g_whlo[49152];

// ---------------- helpers ----------------
__device__ __forceinline__ uint32_t smem_u32(const void* p) {
    uint32_t a;
    asm("{ .reg .u64 t; cvta.to.shared.u64 t, %1; cvt.u32.u64 %0, t; }" : "=r"(a) : "l"(p));
    return a;
}
__device__ __forceinline__ void ldsm4(uint32_t* r, uint32_t addr) {
    asm volatile("ldmatrix.sync.aligned.m8n8.x4.shared.b16 {%0,%1,%2,%3}, [%4];"
                 : "=r"(r[0]), "=r"(r[1]), "=r"(r[2]), "=r"(r[3]) : "r"(addr));
}
__device__ __forceinline__ void mma_bf16(float* d, const uint32_t* a, const uint32_t* b) {
    asm volatile(
        "mma.sync.aligned.m16n8k16.row.col.f32.bf16.bf16.f32 "
        "{%0,%1,%2,%3}, {%4,%5,%6,%7}, {%8,%9}, {%0,%1,%2,%3};"
        : "+f"(d[0]), "+f"(d[1]), "+f"(d[2]), "+f"(d[3])
        : "r"(a[0]), "r"(a[1]), "r"(a[2]), "r"(a[3]), "r"(b[0]), "r"(b[1]));
}
__device__ __forceinline__ void cpa16(uint32_t s, const void* g) {
    asm volatile("cp.async.cg.shared.global [%0], [%1], 16;"
                 :: "r"(s), "l"(__cvta_generic_to_global(g)) : "memory");
}
#define CP_COMMIT() asm volatile("cp.async.commit_group;" ::: "memory")
#define CP_WAIT0()  asm volatile("cp.async.wait_group 0;" ::: "memory")

// pack two fp32 -> bf16x2 (vHI -> upper half, vLO -> lower half)
__device__ __forceinline__ uint32_t pack_bf2(float vHI, float vLO) {
    uint32_t r;
    asm("cvt.rn.bf16x2.f32 %0, %1, %2;" : "=r"(r) : "f"(vHI), "f"(vLO));
    return r;
}
__device__ __forceinline__ float bflo(uint32_t p) { return __uint_as_float(p << 16); }
__device__ __forceinline__ float bfhi(uint32_t p) { return __uint_as_float(p & 0xFFFF0000u); }

__device__ __forceinline__ float fsigmoid(float x) {
    return __fdividef(1.0f, 1.0f + __expf(-x));
}
__device__ __forceinline__ float ftanh(float x) {
    x = fminf(20.0f, fmaxf(-20.0f, x));
    float e = __expf(2.0f * x);
    return __fdividef(e - 1.0f, e + 1.0f);
}

// ---------------------------------------------------------------------------
// Prep: transpose both halves of W to [384][128] K-major, bf16 hi/lo split.
// ---------------------------------------------------------------------------
__global__ void prep_w(const float* __restrict__ gk, const float* __restrict__ ck) {
    int n = blockIdx.x, k = threadIdx.x;
    float vx = (n < 256) ? gk[k * 256 + n] : ck[k * 128 + (n - 256)];
    __nv_bfloat16 hx = __float2bfloat16(vx);
    g_wthi[n * 128 + k] = hx;
    g_wtlo[n * 128 + k] = __float2bfloat16(vx - __bfloat162float(hx));
    float vh = (n < 256) ? gk[(128 + k) * 256 + n] : ck[(128 + k) * 128 + (n - 256)];
    __nv_bfloat16 hh = __float2bfloat16(vh);
    g_whhi[n * 128 + k] = hh;
    g_whlo[n * 128 + k] = __float2bfloat16(vh - __bfloat162float(hh));
}

// ---------------------------------------------------------------------------
// Kernel 1: hoisted x-GEMM on HMMA, bf16x3 split, cp.async double-buffered B.
// Tiles whose whole time-range lies past seqlen[b] are skipped: downstream
// rec masks t >= len (output forced 0, h not updated), so even NaN garbage
// in the skipped scratch region cannot reach the output.
// smem: bias[384f] | Ahi 128x272 | Alo | Bbuf0(hi,lo) | Bbuf1(hi,lo)
// ---------------------------------------------------------------------------
#define A_HI_OFF 1536
#define A_LO_OFF (A_HI_OFF + 34816)
#define B_BUF0   (A_LO_OFF + 34816)
#define B_BUF1   (B_BUF0 + 69632)
#define PRE_SMEM (B_BUF1 + 69632)

__global__ void __launch_bounds__(256) pre_mma(
    const float* __restrict__ X,
    const float* __restrict__ gb, const float* __restrict__ cb,
    const int* __restrict__ seqlen)
{
    extern __shared__ char smc[];
    const uint32_t sb = smem_u32(smc);
    float* biasS = reinterpret_cast<float*>(smc);
    const int tid  = threadIdx.x;
    const int lane = tid & 31;
    const int wid  = tid >> 5;
    const int wm   = wid & 3;
    const int wn   = wid >> 2;
    const int m0   = blockIdx.x * 128;

    // dead-tile skip: this tile covers t in [t0, t0+128) of batch row b
    {
        const int b  = m0 >> 9;          // m0 / 512
        const int t0 = m0 & 511;
        if (t0 >= __ldg(&seqlen[b])) return;
    }

    if (tid < 256) biasS[tid] = gb[tid];
    if (tid < 128) biasS[256 + tid] = cb[tid];

    // ---- issue B tile nt=0 via cp.async ----
    {
        const int row  = tid >> 1;
        const int half = tid & 1;
        uint32_t dHi = sb + B_BUF0 + row * 272 + half * 128;
        uint32_t dLo = dHi + 34816;
        const __nv_bfloat16* sH = &g_wthi[row * 128 + half * 64];
        const __nv_bfloat16* sL = &g_wtlo[row * 128 + half * 64];
        #pragma unroll
        for (int j = 0; j < 8; j++) {
            cpa16(dHi + j * 16, sH + j * 8);
            cpa16(dLo + j * 16, sL + j * 8);
        }
        CP_COMMIT();
    }

    // ---- A tile: fp32 -> bf16 hi/lo, padded rows (272B) ----
    {
        const int row  = tid >> 1;
        const int half = tid & 1;
        const float* xr = &X[(size_t)(m0 + row) * 128 + half * 64];
        char* Ahi = smc + A_HI_OFF + row * 272 + half * 128;
        char* Alo = smc + A_LO_OFF + row * 272 + half * 128;
        #pragma unroll
        for (int j = 0; j < 16; j++) {
            float4 v = *reinterpret_cast<const float4*>(&xr[j * 4]);
            __nv_bfloat162 h01 = __floats2bfloat162_rn(v.x, v.y);
            __nv_bfloat162 h23 = __floats2bfloat162_rn(v.z, v.w);
            __nv_bfloat162 l01 = __floats2bfloat162_rn(v.x - __bfloat162float(h01.x),
                                                       v.y - __bfloat162float(h01.y));
            __nv_bfloat162 l23 = __floats2bfloat162_rn(v.z - __bfloat162float(h23.x),
                                                       v.w - __bfloat162float(h23.y));
            *reinterpret_cast<uint2*>(Ahi + j * 8) =
                make_uint2(*reinterpret_cast<uint32_t*>(&h01), *reinterpret_cast<uint32_t*>(&h23));
            *reinterpret_cast<uint2*>(Alo + j * 8) =
                make_uint2(*reinterpret_cast<uint32_t*>(&l01), *reinterpret_cast<uint32_t*>(&l23));
        }
    }

    const uint32_t aRow0 = sb + A_HI_OFF + (wm * 32 + (lane & 15)) * 272 + (lane >> 4) * 16;
    const uint32_t aRow1 = aRow0 + 16 * 272;
    const uint32_t ALO_D = A_LO_OFF - A_HI_OFF;

    for (int nt = 0; nt < 3; nt++) {
        CP_WAIT0();
        __syncthreads();
        const uint32_t bufC = (nt & 1) ? B_BUF1 : B_BUF0;
        if (nt < 2) {
            const int row  = tid >> 1;
            const int half = tid & 1;
            const uint32_t bufN = (nt & 1) ? B_BUF0 : B_BUF1;
            uint32_t dHi = sb + bufN + row * 272 + half * 128;
            uint32_t dLo = dHi + 34816;
            const __nv_bfloat16* sH = &g_wthi[((nt + 1) * 128 + row) * 128 + half * 64];
            const __nv_bfloat16* sL = &g_wtlo[((nt + 1) * 128 + row) * 128 + half * 64];
            #pragma unroll
            for (int j = 0; j < 8; j++) {
                cpa16(dHi + j * 16, sH + j * 8);
                cpa16(dLo + j * 16, sL + j * 8);
            }
            CP_COMMIT();
        }

        const uint32_t bRowB = sb + bufC
            + (wn * 64 + (lane & 7) + (lane >> 4) * 8) * 272 + ((lane >> 3) & 1) * 16;

        float d[2][8][4];
        #pragma unroll
        for (int mf = 0; mf < 2; mf++)
            #pragma unroll
            for (int nf = 0; nf < 8; nf++)
                #pragma unroll
                for (int e = 0; e < 4; e++) d[mf][nf][e] = 0.0f;

        #pragma unroll
        for (int pass = 0; pass < 3; pass++) {
            const uint32_t aOff = (pass == 2) ? ALO_D : 0u;
            const uint32_t bOff = (pass == 1) ? 34816u : 0u;
            #pragma unroll
            for (int k16 = 0; k16 < 8; k16++) {
                uint32_t a0[4], a1[4];
                ldsm4(a0, aRow0 + aOff + k16 * 32);
                ldsm4(a1, aRow1 + aOff + k16 * 32);
                #pragma unroll
                for (int g = 0; g < 4; g++) {
                    uint32_t bb[4];
                    ldsm4(bb, bRowB + bOff + g * (16 * 272) + k16 * 32);
                    mma_bf16(d[0][2 * g],     a0, bb);
                    mma_bf16(d[0][2 * g + 1], a0, bb + 2);
                    mma_bf16(d[1][2 * g],     a1, bb);
                    mma_bf16(d[1][2 * g + 1], a1, bb + 2);
                }
            }
        }

        {
            const int grp = lane >> 2;
            const int qid = lane & 3;
            #pragma unroll
            for (int nf = 0; nf < 8; nf++) {
                const int cg = wn * 64 + nf * 8 + qid * 2;
                float2 bv = *reinterpret_cast<const float2*>(&biasS[nt * 128 + cg]);
                #pragma unroll
                for (int mf = 0; mf < 2; mf++) {
                    const int r0 = m0 + wm * 32 + mf * 16 + grp;
                    float2 v0 = make_float2(d[mf][nf][0] + bv.x, d[mf][nf][1] + bv.y);
                    float2 v1 = make_float2(d[mf][nf][2] + bv.x, d[mf][nf][3] + bv.y);
                    if (nt < 2) {
                        *reinterpret_cast<float2*>(&g_xg[(size_t)r0 * 256 + nt * 128 + cg]) = v0;
                        *reinterpret_cast<float2*>(&g_xg[(size_t)(r0 + 8) * 256 + nt * 128 + cg]) = v1;
                    } else {
                        *reinterpret_cast<float2*>(&g_xc[(size_t)r0 * 128 + cg]) = v0;
                        *reinterpret_cast<float2*>(&g_xc[(size_t)(r0 + 8) * 128 + cg]) = v1;
                    }
                }
            }
        }
    }
}

// ---------------------------------------------------------------------------
// Kernel 2: recurrent scan on HMMA. 128 CTAs x 8 rows, 512 threads (16 warps).
// Gate W persistent in registers; cand W streamed via ldsm.x4 (hi+lo fused).
// Accumulator chains SPLIT to shorten the HMMA RAW-latency critical path:
// gate by kt-parity (24 -> 12 serial), cand by pass (24 -> 8 serial).
// ---------------------------------------------------------------------------
#define WCHI 0
#define WCLO 34816
#define HHI  69632
#define HLO  71808
#define RHHI 73984
#define RHLO 76160
#define HS   78336
#define US   82560
#define ATTS 86784
#define LENO 103168
#define REC_SMEM 103200

__global__ void __launch_bounds__(512, 1) rec_kernel(
    const float* __restrict__ att,
    const int*   __restrict__ seqlen,
    float* __restrict__ out)
{
    extern __shared__ char smc[];
    const uint32_t sb = smem_u32(smc);
    float* hS   = reinterpret_cast<float*>(smc + HS);    // [8][132] fp32
    float* uS   = reinterpret_cast<float*>(smc + US);    // [8][132] fp32
    float* attS = reinterpret_cast<float*>(smc + ATTS);  // [8][512]
    int*   lenS = reinterpret_cast<int*>(smc + LENO);    // [8]

    const int tid  = threadIdx.x;
    const int lane = tid & 31;
    const int w    = tid >> 5;
    const int b0   = blockIdx.x * 8;

    // stage cand h-side W hi/lo into smem [128 n][272B rows]
    for (int idx = tid; idx < 8192; idx += 512) {
        int rown = idx >> 6, kp = (idx & 63) * 2;
        *reinterpret_cast<uint32_t*>(smc + WCHI + rown * 272 + kp * 2) =
            *reinterpret_cast<const uint32_t*>(&g_whhi[(256 + rown) * 128 + kp]);
        *reinterpret_cast<uint32_t*>(smc + WCLO + rown * 272 + kp * 2) =
            *reinterpret_cast<const uint32_t*>(&g_whlo[(256 + rown) * 128 + kp]);
    }
    // att preload: attS[i][t]
    for (int idx = tid; idx < 4096; idx += 512) {
        int i = idx >> 9, t = idx & 511;
        attS[idx] = att[(b0 + i) * TT + t];
    }
    for (int idx = tid; idx < 1056; idx += 512) hS[idx] = 0.0f;
    for (int idx = tid; idx < 544; idx += 512) {
        reinterpret_cast<uint32_t*>(smc + HHI)[idx] = 0u;
        reinterpret_cast<uint32_t*>(smc + HLO)[idx] = 0u;
    }
    if (tid < 8) lenS[tid] = seqlen[b0 + tid];
    __syncthreads();

    int tmax = 0;
    #pragma unroll
    for (int i = 0; i < 8; i++) tmax = max(tmax, lenS[i]);

    const int row  = lane >> 2;        // 0..7 (batch row within CTA)
    const int colp = (lane & 3) * 2;   // col pair base within n-tile
    const int cw   = w * 16;           // gate col base (w<8: r cols, w>=8: u cols)
    const bool isr = (w < 8);
    const int ccol = w * 8 + colp;     // cand col

    // ---- preload gate W fragments (persistent in registers) ----
    uint32_t wgh[2][8][2], wgl[2][8][2];
    #pragma unroll
    for (int nt = 0; nt < 2; nt++)
        #pragma unroll
        for (int kt = 0; kt < 8; kt++) {
            int n = cw + nt * 8 + (lane >> 2);
            int base = n * 128 + kt * 16 + colp;
            wgh[nt][kt][0] = *reinterpret_cast<const uint32_t*>(&g_whhi[base]);
            wgh[nt][kt][1] = *reinterpret_cast<const uint32_t*>(&g_whhi[base + 8]);
            wgl[nt][kt][0] = *reinterpret_cast<const uint32_t*>(&g_whlo[base]);
            wgl[nt][kt][1] = *reinterpret_cast<const uint32_t*>(&g_whlo[base + 8]);
        }

    // fused hi/lo ldsm.x4 bases: matrices {0,1}=hi, {2,3}=lo
    const uint32_t laneRH = (lane & 7) * 272 + ((lane >> 3) & 1) * 16;
    const uint32_t aAg4 = sb + (lane < 16 ? HHI  : HLO)  + laneRH;
    const uint32_t aAc4 = sb + (lane < 16 ? RHHI : RHLO) + laneRH;
    const uint32_t bAc4 = sb + (lane < 16 ? WCHI : WCLO)
        + (w * 8 + (lane & 7)) * 272 + ((lane >> 3) & 1) * 16;

    const size_t mrB = (size_t)(b0 + row) * TT;
    // pipeline: loads for step t issued at top of step t-1 (here: t=0 preload)
    float2 nxg0 = *reinterpret_cast<const float2*>(&g_xg[mrB * 256 + cw + colp]);
    float2 nxg1 = *reinterpret_cast<const float2*>(&g_xg[mrB * 256 + cw + 8 + colp]);
    float2 nxc  = *reinterpret_cast<const float2*>(&g_xc[mrB * 128 + ccol]);

    for (int t = 0; t < tmax; t++) {
        const float2 xg0 = nxg0, xg1 = nxg1, xc = nxc;
        {   // issue next step's loads (hidden under this whole step)
            const int tn = (t + 1 < tmax) ? t + 1 : t;
            nxg0 = *reinterpret_cast<const float2*>(&g_xg[(mrB + tn) * 256 + cw + colp]);
            nxg1 = *reinterpret_cast<const float2*>(&g_xg[(mrB + tn) * 256 + cw + 8 + colp]);
            nxc  = *reinterpret_cast<const float2*>(&g_xc[(mrB + tn) * 128 + ccol]);
        }

        // ---- gate MMA: 2 n-tiles x 8 kt x 3 passes, kt-parity split chains ----
        float dgA[2][4] = {{0.f, 0.f, 0.f, 0.f}, {0.f, 0.f, 0.f, 0.f}};
        float dgB[2][4] = {{0.f, 0.f, 0.f, 0.f}, {0.f, 0.f, 0.f, 0.f}};
        #pragma unroll
        for (int kt = 0; kt < 8; kt++) {
            uint32_t g4[4];
            ldsm4(g4, aAg4 + kt * 32);
            uint32_t afh[4] = {g4[0], 0u, g4[1], 0u};
            uint32_t afl[4] = {g4[2], 0u, g4[3], 0u};
            float (*dg)[4] = (kt & 1) ? dgB : dgA;
            #pragma unroll
            for (int nt = 0; nt < 2; nt++) {
                mma_bf16(dg[nt], afh, wgh[nt][kt]);
                mma_bf16(dg[nt], afh, wgl[nt][kt]);
                mma_bf16(dg[nt], afl, wgh[nt][kt]);
            }
        }
        // ---- gate epilogue ----
        {
            float s0 = fsigmoid(dgA[0][0] + dgB[0][0] + xg0.x);
            float s1 = fsigmoid(dgA[0][1] + dgB[0][1] + xg0.y);
            float s2 = fsigmoid(dgA[1][0] + dgB[1][0] + xg1.x);
            float s3 = fsigmoid(dgA[1][1] + dgB[1][1] + xg1.y);
            if (isr) {
                int c0 = cw + colp, c1 = cw + 8 + colp;
                float2 ha = *reinterpret_cast<const float2*>(&hS[row * 132 + c0]);
                float2 hb = *reinterpret_cast<const float2*>(&hS[row * 132 + c1]);
                float r0 = s0 * ha.x, r1 = s1 * ha.y;
                float r2 = s2 * hb.x, r3 = s3 * hb.y;
                uint32_t p0 = pack_bf2(r1, r0);
                uint32_t p1 = pack_bf2(r3, r2);
                uint32_t q0 = pack_bf2(r1 - bfhi(p0), r0 - bflo(p0));
                uint32_t q1 = pack_bf2(r3 - bfhi(p1), r2 - bflo(p1));
                *reinterpret_cast<uint32_t*>(smc + RHHI + row * 272 + c0 * 2) = p0;
                *reinterpret_cast<uint32_t*>(smc + RHHI + row * 272 + c1 * 2) = p1;
                *reinterpret_cast<uint32_t*>(smc + RHLO + row * 272 + c0 * 2) = q0;
                *reinterpret_cast<uint32_t*>(smc + RHLO + row * 272 + c1 * 2) = q1;
            } else {
                int c0 = cw - 128 + colp;
                *reinterpret_cast<float2*>(&uS[row * 132 + c0])     = make_float2(s0, s1);
                *reinterpret_cast<float2*>(&uS[row * 132 + c0 + 8]) = make_float2(s2, s3);
            }
        }
        __syncthreads();

        // ---- cand MMA: 1 n-tile x 8 kt x 3 passes, per-pass split chains ----
        float dcA[4] = {0.f, 0.f, 0.f, 0.f};
        float dcB[4] = {0.f, 0.f, 0.f, 0.f};
        float dcC[4] = {0.f, 0.f, 0.f, 0.f};
        #pragma unroll
        for (int kt = 0; kt < 8; kt++) {
            uint32_t a4[4], b4[4];
            ldsm4(a4, aAc4 + kt * 32);
            ldsm4(b4, bAc4 + kt * 32);
            uint32_t afh[4] = {a4[0], 0u, a4[1], 0u};
            uint32_t afl[4] = {a4[2], 0u, a4[3], 0u};
            mma_bf16(dcA, afh, b4);       // hi*hi
            mma_bf16(dcB, afh, b4 + 2);   // hi*lo
            mma_bf16(dcC, afl, b4);       // lo*hi
        }
        // ---- cand epilogue: tanh + attention-gated update + mask + store ----
        {
            float c0 = ftanh(dcA[0] + dcB[0] + dcC[0] + xc.x);
            float c1 = ftanh(dcA[1] + dcB[1] + dcC[1] + xc.y);
            float2 u2 = *reinterpret_cast<const float2*>(&uS[row * 132 + ccol]);
            float2 h2 = *reinterpret_cast<const float2*>(&hS[row * 132 + ccol]);
            float a = attS[row * 512 + t];
            int len = lenS[row];
            float uu0 = (1.0f - a) * u2.x;
            float uu1 = (1.0f - a) * u2.y;
            float n0 = uu0 * h2.x + (1.0f - uu0) * c0;
            float n1 = uu1 * h2.y + (1.0f - uu1) * c1;
            bool mk = (t < len);
            *reinterpret_cast<float2*>(&out[(mrB + t) * 128 + ccol]) =
                mk ? make_float2(n0, n1) : make_float2(0.0f, 0.0f);
            if (mk) {
                *reinterpret_cast<float2*>(&hS[row * 132 + ccol]) = make_float2(n0, n1);
                uint32_t p = pack_bf2(n1, n0);
                uint32_t q = pack_bf2(n1 - bfhi(p), n0 - bflo(p));
                *reinterpret_cast<uint32_t*>(smc + HHI + row * 272 + ccol * 2) = p;
                *reinterpret_cast<uint32_t*>(smc + HLO + row * 272 + ccol * 2) = q;
            }
        }
        __syncthreads();
    }

    // dynamic_rnn zeroes outputs past the sequence length; t >= tmax >= len[i]
    for (int t = tmax; t < TT; t++) {
        for (int idx = tid; idx < 1024; idx += 512) {
            int i = idx >> 7, d = idx & 127;
            out[((size_t)(b0 + i) * TT + t) * 128 + d] = 0.0f;
        }
    }
}

// ---------------------------------------------------------------------------
extern "C" void kernel_launch(void* const* d_in, const int* in_sizes, int n_in,
                              void* d_out, int out_size) {
    const float* x   = (const float*)d_in[0];   // rnn_input [B,T,D]
    const float* att = (const float*)d_in[1];   // att_score [B,T,1]
    const float* gk  = (const float*)d_in[2];   // gate_kernel [2D,2D]
    const float* gb  = (const float*)d_in[3];   // gate_bias [2D]
    const float* ck  = (const float*)d_in[4];   // cand_kernel [2D,D]
    const float* cb  = (const float*)d_in[5];   // cand_bias [D]
    const int*   sl  = (const int*)d_in[6];     // sequence_length [B,1]
    float* out = (float*)d_out;                 // [B,T,D]

    cudaFuncSetAttribute(pre_mma, cudaFuncAttributeMaxDynamicSharedMemorySize, PRE_SMEM);
    cudaFuncSetAttribute(rec_kernel, cudaFuncAttributeMaxDynamicSharedMemorySize, REC_SMEM);

    prep_w<<<384, 128>>>(gk, ck);
    pre_mma<<<(BB * TT) / 128, 256, PRE_SMEM>>>(x, gb, cb, sl);
    rec_kernel<<<BB / 8, 512, REC_SMEM>>>(att, sl, out);
}

// round 16
// speedup vs baseline: 2.8203x; 1.1535x over previous
#include <cuda_runtime.h>
#include <cuda_bf16.h>
#include <cstdint>

// Problem constants
#define BB 1024
#define TT 512
#define DD 128

// Scratch (legal: __device__ globals).
static __device__ float g_xg[134217728];  // B*T*256 : x@Wg_x + gate_bias
static __device__ float g_xc[67108864];   // B*T*128 : x@Wc_x + cand_bias
// x-side W transposed [384][128] K-major, bf16 hi/lo (for pre_mma)
static __device__ __nv_bfloat16 g_wthi[49152];
static __device__ __nv_bfloat16 g_wtlo[49152];
// h-side W transposed [384][128] K-major, bf16 hi/lo (for rec HMMA)
static __device__ __nv_bfloat16 g_whhi[49152];
static __device__ __nv_bfloat16 g_whlo[49152];

// ---------------- helpers ----------------
__device__ __forceinline__ uint32_t smem_u32(const void* p) {
    uint32_t a;
    asm("{ .reg .u64 t; cvta.to.shared.u64 t, %1; cvt.u32.u64 %0, t; }" : "=r"(a) : "l"(p));
    return a;
}
__device__ __forceinline__ void ldsm4(uint32_t* r, uint32_t addr) {
    asm volatile("ldmatrix.sync.aligned.m8n8.x4.shared.b16 {%0,%1,%2,%3}, [%4];"
                 : "=r"(r[0]), "=r"(r[1]), "=r"(r[2]), "=r"(r[3]) : "r"(addr));
}
__device__ __forceinline__ void mma_bf16(float* d, const uint32_t* a, const uint32_t* b) {
    asm volatile(
        "mma.sync.aligned.m16n8k16.row.col.f32.bf16.bf16.f32 "
        "{%0,%1,%2,%3}, {%4,%5,%6,%7}, {%8,%9}, {%0,%1,%2,%3};"
        : "+f"(d[0]), "+f"(d[1]), "+f"(d[2]), "+f"(d[3])
        : "r"(a[0]), "r"(a[1]), "r"(a[2]), "r"(a[3]), "r"(b[0]), "r"(b[1]));
}
__device__ __forceinline__ void cpa16(uint32_t s, const void* g) {
    asm volatile("cp.async.cg.shared.global [%0], [%1], 16;"
                 :: "r"(s), "l"(__cvta_generic_to_global(g)) : "memory");
}
#define CP_COMMIT() asm volatile("cp.async.commit_group;" ::: "memory")
#define CP_WAIT0()  asm volatile("cp.async.wait_group 0;" ::: "memory")

// pack two fp32 -> bf16x2 (vHI -> upper half, vLO -> lower half)
__device__ __forceinline__ uint32_t pack_bf2(float vHI, float vLO) {
    uint32_t r;
    asm("cvt.rn.bf16x2.f32 %0, %1, %2;" : "=r"(r) : "f"(vHI), "f"(vLO));
    return r;
}
__device__ __forceinline__ float bflo(uint32_t p) { return __uint_as_float(p << 16); }
__device__ __forceinline__ float bfhi(uint32_t p) { return __uint_as_float(p & 0xFFFF0000u); }

__device__ __forceinline__ float fsigmoid(float x) {
    return __fdividef(1.0f, 1.0f + __expf(-x));
}
__device__ __forceinline__ float ftanh(float x) {
    x = fminf(20.0f, fmaxf(-20.0f, x));
    float e = __expf(2.0f * x);
    return __fdividef(e - 1.0f, e + 1.0f);
}

// ---------------------------------------------------------------------------
// Prep: transpose both halves of W to [384][128] K-major, bf16 hi/lo split.
// ---------------------------------------------------------------------------
__global__ void prep_w(const float* __restrict__ gk, const float* __restrict__ ck) {
    int n = blockIdx.x, k = threadIdx.x;
    float vx = (n < 256) ? gk[k * 256 + n] : ck[k * 128 + (n - 256)];
    __nv_bfloat16 hx = __float2bfloat16(vx);
    g_wthi[n * 128 + k] = hx;
    g_wtlo[n * 128 + k] = __float2bfloat16(vx - __bfloat162float(hx));
    float vh = (n < 256) ? gk[(128 + k) * 256 + n] : ck[(128 + k) * 128 + (n - 256)];
    __nv_bfloat16 hh = __float2bfloat16(vh);
    g_whhi[n * 128 + k] = hh;
    g_whlo[n * 128 + k] = __float2bfloat16(vh - __bfloat162float(hh));
}

// ---------------------------------------------------------------------------
// Kernel 1: hoisted x-GEMM on HMMA, bf16x3 split, cp.async double-buffered B.
// Dead tiles (t0 >= seqlen[b]) skipped. (unchanged from R15 — passing)
// ---------------------------------------------------------------------------
#define A_HI_OFF 1536
#define A_LO_OFF (A_HI_OFF + 34816)
#define B_BUF0   (A_LO_OFF + 34816)
#define B_BUF1   (B_BUF0 + 69632)
#define PRE_SMEM (B_BUF1 + 69632)

__global__ void __launch_bounds__(256) pre_mma(
    const float* __restrict__ X,
    const float* __restrict__ gb, const float* __restrict__ cb,
    const int* __restrict__ seqlen)
{
    extern __shared__ char smc[];
    const uint32_t sb = smem_u32(smc);
    float* biasS = reinterpret_cast<float*>(smc);
    const int tid  = threadIdx.x;
    const int lane = tid & 31;
    const int wid  = tid >> 5;
    const int wm   = wid & 3;
    const int wn   = wid >> 2;
    const int m0   = blockIdx.x * 128;

    {
        const int b  = m0 >> 9;
        const int t0 = m0 & 511;
        if (t0 >= __ldg(&seqlen[b])) return;
    }

    if (tid < 256) biasS[tid] = gb[tid];
    if (tid < 128) biasS[256 + tid] = cb[tid];

    {
        const int row  = tid >> 1;
        const int half = tid & 1;
        uint32_t dHi = sb + B_BUF0 + row * 272 + half * 128;
        uint32_t dLo = dHi + 34816;
        const __nv_bfloat16* sH = &g_wthi[row * 128 + half * 64];
        const __nv_bfloat16* sL = &g_wtlo[row * 128 + half * 64];
        #pragma unroll
        for (int j = 0; j < 8; j++) {
            cpa16(dHi + j * 16, sH + j * 8);
            cpa16(dLo + j * 16, sL + j * 8);
        }
        CP_COMMIT();
    }

    {
        const int row  = tid >> 1;
        const int half = tid & 1;
        const float* xr = &X[(size_t)(m0 + row) * 128 + half * 64];
        char* Ahi = smc + A_HI_OFF + row * 272 + half * 128;
        char* Alo = smc + A_LO_OFF + row * 272 + half * 128;
        #pragma unroll
        for (int j = 0; j < 16; j++) {
            float4 v = *reinterpret_cast<const float4*>(&xr[j * 4]);
            __nv_bfloat162 h01 = __floats2bfloat162_rn(v.x, v.y);
            __nv_bfloat162 h23 = __floats2bfloat162_rn(v.z, v.w);
            __nv_bfloat162 l01 = __floats2bfloat162_rn(v.x - __bfloat162float(h01.x),
                                                       v.y - __bfloat162float(h01.y));
            __nv_bfloat162 l23 = __floats2bfloat162_rn(v.z - __bfloat162float(h23.x),
                                                       v.w - __bfloat162float(h23.y));
            *reinterpret_cast<uint2*>(Ahi + j * 8) =
                make_uint2(*reinterpret_cast<uint32_t*>(&h01), *reinterpret_cast<uint32_t*>(&h23));
            *reinterpret_cast<uint2*>(Alo + j * 8) =
                make_uint2(*reinterpret_cast<uint32_t*>(&l01), *reinterpret_cast<uint32_t*>(&l23));
        }
    }

    const uint32_t aRow0 = sb + A_HI_OFF + (wm * 32 + (lane & 15)) * 272 + (lane >> 4) * 16;
    const uint32_t aRow1 = aRow0 + 16 * 272;
    const uint32_t ALO_D = A_LO_OFF - A_HI_OFF;

    for (int nt = 0; nt < 3; nt++) {
        CP_WAIT0();
        __syncthreads();
        const uint32_t bufC = (nt & 1) ? B_BUF1 : B_BUF0;
        if (nt < 2) {
            const int row  = tid >> 1;
            const int half = tid & 1;
            const uint32_t bufN = (nt & 1) ? B_BUF0 : B_BUF1;
            uint32_t dHi = sb + bufN + row * 272 + half * 128;
            uint32_t dLo = dHi + 34816;
            const __nv_bfloat16* sH = &g_wthi[((nt + 1) * 128 + row) * 128 + half * 64];
            const __nv_bfloat16* sL = &g_wtlo[((nt + 1) * 128 + row) * 128 + half * 64];
            #pragma unroll
            for (int j = 0; j < 8; j++) {
                cpa16(dHi + j * 16, sH + j * 8);
                cpa16(dLo + j * 16, sL + j * 8);
            }
            CP_COMMIT();
        }

        const uint32_t bRowB = sb + bufC
            + (wn * 64 + (lane & 7) + (lane >> 4) * 8) * 272 + ((lane >> 3) & 1) * 16;

        float d[2][8][4];
        #pragma unroll
        for (int mf = 0; mf < 2; mf++)
            #pragma unroll
            for (int nf = 0; nf < 8; nf++)
                #pragma unroll
                for (int e = 0; e < 4; e++) d[mf][nf][e] = 0.0f;

        #pragma unroll
        for (int pass = 0; pass < 3; pass++) {
            const uint32_t aOff = (pass == 2) ? ALO_D : 0u;
            const uint32_t bOff = (pass == 1) ? 34816u : 0u;
            #pragma unroll
            for (int k16 = 0; k16 < 8; k16++) {
                uint32_t a0[4], a1[4];
                ldsm4(a0, aRow0 + aOff + k16 * 32);
                ldsm4(a1, aRow1 + aOff + k16 * 32);
                #pragma unroll
                for (int g = 0; g < 4; g++) {
                    uint32_t bb[4];
                    ldsm4(bb, bRowB + bOff + g * (16 * 272) + k16 * 32);
                    mma_bf16(d[0][2 * g],     a0, bb);
                    mma_bf16(d[0][2 * g + 1], a0, bb + 2);
                    mma_bf16(d[1][2 * g],     a1, bb);
                    mma_bf16(d[1][2 * g + 1], a1, bb + 2);
                }
            }
        }

        {
            const int grp = lane >> 2;
            const int qid = lane & 3;
            #pragma unroll
            for (int nf = 0; nf < 8; nf++) {
                const int cg = wn * 64 + nf * 8 + qid * 2;
                float2 bv = *reinterpret_cast<const float2*>(&biasS[nt * 128 + cg]);
                #pragma unroll
                for (int mf = 0; mf < 2; mf++) {
                    const int r0 = m0 + wm * 32 + mf * 16 + grp;
                    float2 v0 = make_float2(d[mf][nf][0] + bv.x, d[mf][nf][1] + bv.y);
                    float2 v1 = make_float2(d[mf][nf][2] + bv.x, d[mf][nf][3] + bv.y);
                    if (nt < 2) {
                        *reinterpret_cast<float2*>(&g_xg[(size_t)r0 * 256 + nt * 128 + cg]) = v0;
                        *reinterpret_cast<float2*>(&g_xg[(size_t)(r0 + 8) * 256 + nt * 128 + cg]) = v1;
                    } else {
                        *reinterpret_cast<float2*>(&g_xc[(size_t)r0 * 128 + cg]) = v0;
                        *reinterpret_cast<float2*>(&g_xc[(size_t)(r0 + 8) * 128 + cg]) = v1;
                    }
                }
            }
        }
    }
}

// ---------------------------------------------------------------------------
// Kernel 2: recurrent scan on HMMA, hi/lo PACKED IN M (rows 0-7 = h_hi,
// rows 8-15 = h_lo). One MMA vs W_hi + one vs W_lo covers all 4 split terms
// (incl. lo*lo): result = d[0]+d[2]. Gate 32 MMA/warp/step, cand 16 (was 48/24).
// Gate W persistent in registers; cand W streamed via ldsm.x4 (hi+lo fused).
// ---------------------------------------------------------------------------
#define WCHI 0
#define WCLO 34816
#define HHI  69632
#define HLO  71808
#define RHHI 73984
#define RHLO 76160
#define HS   78336
#define US   82560
#define ATTS 86784
#define LENO 103168
#define REC_SMEM 103200

__global__ void __launch_bounds__(512, 1) rec_kernel(
    const float* __restrict__ att,
    const int*   __restrict__ seqlen,
    float* __restrict__ out)
{
    extern __shared__ char smc[];
    const uint32_t sb = smem_u32(smc);
    float* hS   = reinterpret_cast<float*>(smc + HS);    // [8][132] fp32
    float* uS   = reinterpret_cast<float*>(smc + US);    // [8][132] fp32
    float* attS = reinterpret_cast<float*>(smc + ATTS);  // [8][512]
    int*   lenS = reinterpret_cast<int*>(smc + LENO);    // [8]

    const int tid  = threadIdx.x;
    const int lane = tid & 31;
    const int w    = tid >> 5;
    const int b0   = blockIdx.x * 8;

    // stage cand h-side W hi/lo into smem [128 n][272B rows]
    for (int idx = tid; idx < 8192; idx += 512) {
        int rown = idx >> 6, kp = (idx & 63) * 2;
        *reinterpret_cast<uint32_t*>(smc + WCHI + rown * 272 + kp * 2) =
            *reinterpret_cast<const uint32_t*>(&g_whhi[(256 + rown) * 128 + kp]);
        *reinterpret_cast<uint32_t*>(smc + WCLO + rown * 272 + kp * 2) =
            *reinterpret_cast<const uint32_t*>(&g_whlo[(256 + rown) * 128 + kp]);
    }
    // att preload: attS[i][t]
    for (int idx = tid; idx < 4096; idx += 512) {
        int i = idx >> 9, t = idx & 511;
        attS[idx] = att[(b0 + i) * TT + t];
    }
    for (int idx = tid; idx < 1056; idx += 512) hS[idx] = 0.0f;
    for (int idx = tid; idx < 544; idx += 512) {
        reinterpret_cast<uint32_t*>(smc + HHI)[idx] = 0u;
        reinterpret_cast<uint32_t*>(smc + HLO)[idx] = 0u;
    }
    if (tid < 8) lenS[tid] = seqlen[b0 + tid];
    __syncthreads();

    int tmax = 0;
    #pragma unroll
    for (int i = 0; i < 8; i++) tmax = max(tmax, lenS[i]);

    const int row  = lane >> 2;        // 0..7 (batch row within CTA)
    const int colp = (lane & 3) * 2;   // col pair base within n-tile
    const int cw   = w * 16;           // gate col base (w<8: r cols, w>=8: u cols)
    const bool isr = (w < 8);
    const int ccol = w * 8 + colp;     // cand col

    // ---- preload gate W fragments (persistent in registers) ----
    uint32_t wgh[2][8][2], wgl[2][8][2];
    #pragma unroll
    for (int nt = 0; nt < 2; nt++)
        #pragma unroll
        for (int kt = 0; kt < 8; kt++) {
            int n = cw + nt * 8 + (lane >> 2);
            int base = n * 128 + kt * 16 + colp;
            wgh[nt][kt][0] = *reinterpret_cast<const uint32_t*>(&g_whhi[base]);
            wgh[nt][kt][1] = *reinterpret_cast<const uint32_t*>(&g_whhi[base + 8]);
            wgl[nt][kt][0] = *reinterpret_cast<const uint32_t*>(&g_whlo[base]);
            wgl[nt][kt][1] = *reinterpret_cast<const uint32_t*>(&g_whlo[base + 8]);
        }

    // fused hi/lo ldsm.x4 bases: matrices {0,1}=hi{k0-7,k8-15}, {2,3}=lo
    const uint32_t laneRH = (lane & 7) * 272 + ((lane >> 3) & 1) * 16;
    const uint32_t aAg4 = sb + (lane < 16 ? HHI  : HLO)  + laneRH;
    const uint32_t aAc4 = sb + (lane < 16 ? RHHI : RHLO) + laneRH;
    const uint32_t bAc4 = sb + (lane < 16 ? WCHI : WCLO)
        + (w * 8 + (lane & 7)) * 272 + ((lane >> 3) & 1) * 16;

    const size_t mrB = (size_t)(b0 + row) * TT;
    // pipeline: loads for step t issued at top of step t-1 (here: t=0 preload)
    float2 nxg0 = *reinterpret_cast<const float2*>(&g_xg[mrB * 256 + cw + colp]);
    float2 nxg1 = *reinterpret_cast<const float2*>(&g_xg[mrB * 256 + cw + 8 + colp]);
    float2 nxc  = *reinterpret_cast<const float2*>(&g_xc[mrB * 128 + ccol]);

    for (int t = 0; t < tmax; t++) {
        const float2 xg0 = nxg0, xg1 = nxg1, xc = nxc;
        {   // issue next step's loads (hidden under this whole step)
            const int tn = (t + 1 < tmax) ? t + 1 : t;
            nxg0 = *reinterpret_cast<const float2*>(&g_xg[(mrB + tn) * 256 + cw + colp]);
            nxg1 = *reinterpret_cast<const float2*>(&g_xg[(mrB + tn) * 256 + cw + 8 + colp]);
            nxc  = *reinterpret_cast<const float2*>(&g_xc[(mrB + tn) * 128 + ccol]);
        }

        // ---- gate MMA: A = [h_hi | h_lo] packed in M; 2 MMA per (nt,kt) ----
        float dgA[2][4] = {{0.f, 0.f, 0.f, 0.f}, {0.f, 0.f, 0.f, 0.f}};
        float dgB[2][4] = {{0.f, 0.f, 0.f, 0.f}, {0.f, 0.f, 0.f, 0.f}};
        #pragma unroll
        for (int kt = 0; kt < 8; kt++) {
            uint32_t g4[4];
            ldsm4(g4, aAg4 + kt * 32);
            // a0=hi k0-7, a1=lo k0-7, a2=hi k8-15, a3=lo k8-15
            uint32_t af[4] = {g4[0], g4[2], g4[1], g4[3]};
            float (*dg)[4] = (kt & 1) ? dgB : dgA;
            #pragma unroll
            for (int nt = 0; nt < 2; nt++) {
                mma_bf16(dg[nt], af, wgh[nt][kt]);   // hi*Whi (rows0-7) + lo*Whi (rows8-15)
                mma_bf16(dg[nt], af, wgl[nt][kt]);   // hi*Wlo + lo*Wlo
            }
        }
        // ---- gate epilogue: real result = d[0]+d[2] (row g = hi + lo rows) ----
        {
            float s0 = fsigmoid(dgA[0][0] + dgA[0][2] + dgB[0][0] + dgB[0][2] + xg0.x);
            float s1 = fsigmoid(dgA[0][1] + dgA[0][3] + dgB[0][1] + dgB[0][3] + xg0.y);
            float s2 = fsigmoid(dgA[1][0] + dgA[1][2] + dgB[1][0] + dgB[1][2] + xg1.x);
            float s3 = fsigmoid(dgA[1][1] + dgA[1][3] + dgB[1][1] + dgB[1][3] + xg1.y);
            if (isr) {
                int c0 = cw + colp, c1 = cw + 8 + colp;
                float2 ha = *reinterpret_cast<const float2*>(&hS[row * 132 + c0]);
                float2 hb = *reinterpret_cast<const float2*>(&hS[row * 132 + c1]);
                float r0 = s0 * ha.x, r1 = s1 * ha.y;
                float r2 = s2 * hb.x, r3 = s3 * hb.y;
                uint32_t p0 = pack_bf2(r1, r0);
                uint32_t p1 = pack_bf2(r3, r2);
                uint32_t q0 = pack_bf2(r1 - bfhi(p0), r0 - bflo(p0));
                uint32_t q1 = pack_bf2(r3 - bfhi(p1), r2 - bflo(p1));
                *reinterpret_cast<uint32_t*>(smc + RHHI + row * 272 + c0 * 2) = p0;
                *reinterpret_cast<uint32_t*>(smc + RHHI + row * 272 + c1 * 2) = p1;
                *reinterpret_cast<uint32_t*>(smc + RHLO + row * 272 + c0 * 2) = q0;
                *reinterpret_cast<uint32_t*>(smc + RHLO + row * 272 + c1 * 2) = q1;
            } else {
                int c0 = cw - 128 + colp;
                *reinterpret_cast<float2*>(&uS[row * 132 + c0])     = make_float2(s0, s1);
                *reinterpret_cast<float2*>(&uS[row * 132 + c0 + 8]) = make_float2(s2, s3);
            }
        }
        __syncthreads();

        // ---- cand MMA: A = [rh_hi | rh_lo] packed; 2 MMA per kt ----
        float dcA[4] = {0.f, 0.f, 0.f, 0.f};
        float dcB[4] = {0.f, 0.f, 0.f, 0.f};
        #pragma unroll
        for (int kt = 0; kt < 8; kt++) {
            uint32_t a4[4], b4[4];
            ldsm4(a4, aAc4 + kt * 32);
            ldsm4(b4, bAc4 + kt * 32);
            uint32_t af[4] = {a4[0], a4[2], a4[1], a4[3]};
            mma_bf16(dcA, af, b4);       // *Wc_hi
            mma_bf16(dcB, af, b4 + 2);   // *Wc_lo
        }
        // ---- cand epilogue: tanh + attention-gated update + mask + store ----
        {
            float c0 = ftanh(dcA[0] + dcA[2] + dcB[0] + dcB[2] + xc.x);
            float c1 = ftanh(dcA[1] + dcA[3] + dcB[1] + dcB[3] + xc.y);
            float2 u2 = *reinterpret_cast<const float2*>(&uS[row * 132 + ccol]);
            float2 h2 = *reinterpret_cast<const float2*>(&hS[row * 132 + ccol]);
            float a = attS[row * 512 + t];
            int len = lenS[row];
            float uu0 = (1.0f - a) * u2.x;
            float uu1 = (1.0f - a) * u2.y;
            float n0 = uu0 * h2.x + (1.0f - uu0) * c0;
            float n1 = uu1 * h2.y + (1.0f - uu1) * c1;
            bool mk = (t < len);
            *reinterpret_cast<float2*>(&out[(mrB + t) * 128 + ccol]) =
                mk ? make_float2(n0, n1) : make_float2(0.0f, 0.0f);
            if (mk) {
                *reinterpret_cast<float2*>(&hS[row * 132 + ccol]) = make_float2(n0, n1);
                uint32_t p = pack_bf2(n1, n0);
                uint32_t q = pack_bf2(n1 - bfhi(p), n0 - bflo(p));
                *reinterpret_cast<uint32_t*>(smc + HHI + row * 272 + ccol * 2) = p;
                *reinterpret_cast<uint32_t*>(smc + HLO + row * 272 + ccol * 2) = q;
            }
        }
        __syncthreads();
    }

    // dynamic_rnn zeroes outputs past the sequence length; t >= tmax >= len[i]
    for (int t = tmax; t < TT; t++) {
        for (int idx = tid; idx < 1024; idx += 512) {
            int i = idx >> 7, d = idx & 127;
            out[((size_t)(b0 + i) * TT + t) * 128 + d] = 0.0f;
        }
    }
}

// ---------------------------------------------------------------------------
extern "C" void kernel_launch(void* const* d_in, const int* in_sizes, int n_in,
                              void* d_out, int out_size) {
    const float* x   = (const float*)d_in[0];   // rnn_input [B,T,D]
    const float* att = (const float*)d_in[1];   // att_score [B,T,1]
    const float* gk  = (const float*)d_in[2];   // gate_kernel [2D,2D]
    const float* gb  = (const float*)d_in[3];   // gate_bias [2D]
    const float* ck  = (const float*)d_in[4];   // cand_kernel [2D,D]
    const float* cb  = (const float*)d_in[5];   // cand_bias [D]
    const int*   sl  = (const int*)d_in[6];     // sequence_length [B,1]
    float* out = (float*)d_out;                 // [B,T,D]

    cudaFuncSetAttribute(pre_mma, cudaFuncAttributeMaxDynamicSharedMemorySize, PRE_SMEM);
    cudaFuncSetAttribute(rec_kernel, cudaFuncAttributeMaxDynamicSharedMemorySize, REC_SMEM);

    prep_w<<<384, 128>>>(gk, ck);
    pre_mma<<<(BB * TT) / 128, 256, PRE_SMEM>>>(x, gb, cb, sl);
    rec_kernel<<<BB / 8, 512, REC_SMEM>>>(att, sl, out);
}